// round 1
// baseline (speedup 1.0000x reference)
#include <cuda_runtime.h>
#include <math.h>

#define TT 512
#define BB 64
#define DD 512
#define HH 512
#define DH 1024
#define NG 2048          // 4*H gate rows
#define NPRE 2560        // gates + residual rows

// ---------------- scratch (device globals; no allocations) ----------------
__device__ float g_Wx[(size_t)NPRE * DD];              // packed x-side weights (gate-major) + W_r
__device__ float g_Wh[(size_t)NG * HH];                // packed h-side weights (gate-major)
__device__ float g_bias[NPRE];
__device__ float g_pre[(size_t)TT * NPRE * BB];        // pre-activations incl. bias + residual
__device__ float g_c[BB * HH];                         // cell state

// ---------------- pack weights + zero cell state ----------------
__global__ void pack_kernel(const float* __restrict__ Wf, const float* __restrict__ bf,
                            const float* __restrict__ Wi, const float* __restrict__ bi,
                            const float* __restrict__ Wg, const float* __restrict__ bg,
                            const float* __restrict__ Wo, const float* __restrict__ bo,
                            const float* __restrict__ Wr, const float* __restrict__ br) {
    int idx = blockIdx.x * blockDim.x + threadIdx.x;
    int stride = gridDim.x * blockDim.x;
    // x-side weights (rows 0..2047: gates f,i,g,o; rows 2048..2559: W_r)
    for (int i = idx; i < NPRE * DD; i += stride) {
        int n = i / DD, d = i - n * DD;
        float v;
        if (n < NG) {
            int gate = n >> 9, h = n & 511;
            const float* W = (gate == 0) ? Wf : (gate == 1) ? Wi : (gate == 2) ? Wg : Wo;
            v = W[h * DH + d];
        } else {
            v = Wr[(n - NG) * DD + d];
        }
        g_Wx[i] = v;
    }
    // h-side weights
    for (int i = idx; i < NG * HH; i += stride) {
        int n = i / HH, k = i - n * HH;
        int gate = n >> 9, h = n & 511;
        const float* W = (gate == 0) ? Wf : (gate == 1) ? Wi : (gate == 2) ? Wg : Wo;
        g_Wh[i] = W[h * DH + DD + k];
    }
    // biases
    for (int i = idx; i < NPRE; i += stride) {
        float v;
        if (i < NG) {
            int gate = i >> 9, h = i & 511;
            v = (gate == 0) ? bf[h] : (gate == 1) ? bi[h] : (gate == 2) ? bg[h] : bo[h];
        } else {
            v = br[i - NG];
        }
        g_bias[i] = v;
    }
    // zero cell state (must happen every graph replay)
    for (int i = idx; i < BB * HH; i += stride) g_c[i] = 0.0f;
}

// ---------------- batched input-side GEMM ----------------
// pre[t, n, b] = sum_d g_Wx[n,d] * x[t,b,d] + bias[n]
// grid: (NPRE/64, T); block: 256 (16x16), 4x4 microtile
__global__ void __launch_bounds__(256) pre_gemm(const float* __restrict__ x) {
    const int t = blockIdx.y;
    const int nBase = blockIdx.x * 64;
    __shared__ float sW[16][64];
    __shared__ float sX[16][64];
    const int tid = threadIdx.x;
    const int tx = tid & 15, ty = tid >> 4;
    float acc[4][4] = {};
    const float* xt = x + (size_t)t * BB * DD;

    const int ldr = tid >> 2;          // 0..63 : n-local / b index for loads
    const int kk  = (tid & 3) * 4;     // 0,4,8,12

    for (int kc = 0; kc < DD; kc += 16) {
        // load W tile [64n x 16k] -> sW[k][n]
        {
            float4 w = *(const float4*)&g_Wx[(size_t)(nBase + ldr) * DD + kc + kk];
            sW[kk + 0][ldr] = w.x; sW[kk + 1][ldr] = w.y;
            sW[kk + 2][ldr] = w.z; sW[kk + 3][ldr] = w.w;
            float4 xv = *(const float4*)&xt[ldr * DD + kc + kk];
            sX[kk + 0][ldr] = xv.x; sX[kk + 1][ldr] = xv.y;
            sX[kk + 2][ldr] = xv.z; sX[kk + 3][ldr] = xv.w;
        }
        __syncthreads();
#pragma unroll
        for (int k = 0; k < 16; k++) {
            float4 w  = *(const float4*)&sW[k][ty * 4];
            float4 xv = *(const float4*)&sX[k][tx * 4];
            acc[0][0] += w.x * xv.x; acc[0][1] += w.x * xv.y; acc[0][2] += w.x * xv.z; acc[0][3] += w.x * xv.w;
            acc[1][0] += w.y * xv.x; acc[1][1] += w.y * xv.y; acc[1][2] += w.y * xv.z; acc[1][3] += w.y * xv.w;
            acc[2][0] += w.z * xv.x; acc[2][1] += w.z * xv.y; acc[2][2] += w.z * xv.z; acc[2][3] += w.z * xv.w;
            acc[3][0] += w.w * xv.x; acc[3][1] += w.w * xv.y; acc[3][2] += w.w * xv.z; acc[3][3] += w.w * xv.w;
        }
        __syncthreads();
    }
    size_t base = (size_t)t * NPRE * BB;
#pragma unroll
    for (int i = 0; i < 4; i++) {
        int n = nBase + ty * 4 + i;
        float bv = g_bias[n];
        float4 o;
        o.x = acc[i][0] + bv; o.y = acc[i][1] + bv;
        o.z = acc[i][2] + bv; o.w = acc[i][3] + bv;
        *(float4*)&g_pre[base + (size_t)n * BB + tx * 4] = o;
    }
}

// ---------------- per-timestep kernel ----------------
// grid: (32 col-blocks x 4 batch-blocks) = 128 CTAs; block 128 threads.
// Each CTA: 16 h-columns x 16 batches -> 64 gate rows x 16 b GEMM over K=512,
// then the elementwise LSTM cell update (writes h_t into out[t], c into g_c).
__global__ void __launch_bounds__(128) step_kernel(const float* __restrict__ h_prev,
                                                   float* __restrict__ out, int t) {
    const int jc = blockIdx.x * 16;   // h-column base
    const int bb = blockIdx.y * 16;   // batch base
    const int tid = threadIdx.x;
    __shared__ float sW[32][64];      // [k][row]  (row = gate*16 + col_local)
    __shared__ float sH[32][16];      // [k][b_local]
    __shared__ float sAcc[64][16];

    float acc[4][2] = {};
    const int rg = tid >> 3;          // 0..15 : row group (4 rows)  / also load col & b index
    const int bg = tid & 7;           // 0..7  : b pair
    const int k4 = (tid & 7) * 4;     // k offset for loads

    if (t > 0) {
        for (int kc = 0; kc < HH; kc += 32) {
            // weights: row r = s*16 + rg  ->  n = s*512 + jc + rg
#pragma unroll
            for (int s = 0; s < 4; s++) {
                int n = s * 512 + jc + rg;
                float4 w = *(const float4*)&g_Wh[(size_t)n * HH + kc + k4];
                sW[k4 + 0][s * 16 + rg] = w.x;
                sW[k4 + 1][s * 16 + rg] = w.y;
                sW[k4 + 2][s * 16 + rg] = w.z;
                sW[k4 + 3][s * 16 + rg] = w.w;
            }
            // h tile: b_local = rg (0..15)
            {
                float4 hv = *(const float4*)&h_prev[(size_t)(bb + rg) * HH + kc + k4];
                sH[k4 + 0][rg] = hv.x; sH[k4 + 1][rg] = hv.y;
                sH[k4 + 2][rg] = hv.z; sH[k4 + 3][rg] = hv.w;
            }
            __syncthreads();
#pragma unroll
            for (int k = 0; k < 32; k++) {
                float4 w  = *(const float4*)&sW[k][rg * 4];
                float2 hv = *(const float2*)&sH[k][bg * 2];
                acc[0][0] += w.x * hv.x; acc[0][1] += w.x * hv.y;
                acc[1][0] += w.y * hv.x; acc[1][1] += w.y * hv.y;
                acc[2][0] += w.z * hv.x; acc[2][1] += w.z * hv.y;
                acc[3][0] += w.w * hv.x; acc[3][1] += w.w * hv.y;
            }
            __syncthreads();
        }
    }
    // park partial gate pre-activations in smem for the elementwise phase
#pragma unroll
    for (int i = 0; i < 4; i++) {
        sAcc[rg * 4 + i][bg * 2 + 0] = acc[i][0];
        sAcc[rg * 4 + i][bg * 2 + 1] = acc[i][1];
    }
    __syncthreads();

    const size_t preBase = (size_t)t * NPRE * BB;
#pragma unroll
    for (int u = 0; u < 2; u++) {
        int idx = tid + u * 128;      // 0..255
        int col = idx >> 4;           // 0..15
        int b   = idx & 15;
        int n0  = jc + col;
        int gb  = bb + b;
        float fp = sAcc[col][b]      + g_pre[preBase + (size_t)(n0)          * BB + gb];
        float ip = sAcc[16 + col][b] + g_pre[preBase + (size_t)(512 + n0)    * BB + gb];
        float gp = sAcc[32 + col][b] + g_pre[preBase + (size_t)(1024 + n0)   * BB + gb];
        float op = sAcc[48 + col][b] + g_pre[preBase + (size_t)(1536 + n0)   * BB + gb];
        float rv =                     g_pre[preBase + (size_t)(2048 + n0)   * BB + gb];
        float f  = 1.0f / (1.0f + expf(-fp));
        float ii = 1.0f / (1.0f + expf(-ip));
        float gg = tanhf(gp);
        float oo = 1.0f / (1.0f + expf(-op));
        int ci = gb * HH + n0;
        float cnew = f * g_c[ci] + ii * gg;
        g_c[ci] = cnew;
        out[(size_t)t * BB * HH + (size_t)gb * HH + n0] = oo * tanhf(cnew) + rv;
    }
}

// ---------------- tail: append (hx, cx) after stacked outputs ----------------
__global__ void tail_kernel(float* __restrict__ out) {
    int i = blockIdx.x * blockDim.x + threadIdx.x;
    if (i < BB * HH) {
        out[(size_t)TT * BB * HH + i]           = out[(size_t)(TT - 1) * BB * HH + i];
        out[(size_t)TT * BB * HH + BB * HH + i] = g_c[i];
    }
}

extern "C" void kernel_launch(void* const* d_in, const int* in_sizes, int n_in,
                              void* d_out, int out_size) {
    const float* x  = (const float*)d_in[0];
    const float* Wf = (const float*)d_in[1];
    const float* bf = (const float*)d_in[2];
    const float* Wi = (const float*)d_in[3];
    const float* bi = (const float*)d_in[4];
    const float* Wg = (const float*)d_in[5];
    const float* bg = (const float*)d_in[6];
    const float* Wo = (const float*)d_in[7];
    const float* bo = (const float*)d_in[8];
    const float* Wr = (const float*)d_in[9];
    const float* br = (const float*)d_in[10];
    float* out = (float*)d_out;

    pack_kernel<<<256, 256>>>(Wf, bf, Wi, bi, Wg, bg, Wo, bo, Wr, br);
    pre_gemm<<<dim3(NPRE / 64, TT), 256>>>(x);
    for (int t = 0; t < TT; t++) {
        const float* hp = (t == 0) ? nullptr : out + (size_t)(t - 1) * BB * HH;
        step_kernel<<<dim3(32, 4), 128>>>(hp, out, t);
    }
    if (out_size >= TT * BB * HH + 2 * BB * HH)
        tail_kernel<<<(BB * HH + 255) / 256, 256>>>(out);
}

// round 2
// speedup vs baseline: 1.4310x; 1.4310x over previous
#include <cuda_runtime.h>
#include <math.h>

#define TT 512
#define BB 64
#define DD 512
#define HH 512
#define DH 1024
#define NG 2048          // 4*H gate rows
#define NPRE 2560        // gates + residual rows
#define NCTA 128

// ---------------- scratch (device globals; no allocations) ----------------
__device__ float g_Wx[(size_t)NPRE * DD];        // packed x-side weights (gate-major) + W_r
__device__ float g_Wh[(size_t)NG * HH];          // packed h-side weights (gate-major)
__device__ float g_bias[NPRE];
__device__ float g_pre[(size_t)TT * NPRE * BB];  // pre-activations incl. bias + residual
__device__ float g_part[4 * (size_t)NG * BB];    // K-split partial sums [kb][n][b]
__device__ float g_c[BB * HH];                   // final cell state
__device__ unsigned g_bar_count;
__device__ unsigned g_bar_gen;

// ---------------- pack weights ----------------
__global__ void pack_kernel(const float* __restrict__ Wf, const float* __restrict__ bf,
                            const float* __restrict__ Wi, const float* __restrict__ bi,
                            const float* __restrict__ Wg, const float* __restrict__ bg,
                            const float* __restrict__ Wo, const float* __restrict__ bo,
                            const float* __restrict__ Wr, const float* __restrict__ br) {
    int idx = blockIdx.x * blockDim.x + threadIdx.x;
    int stride = gridDim.x * blockDim.x;
    for (int i = idx; i < NPRE * DD; i += stride) {
        int n = i / DD, d = i - n * DD;
        float v;
        if (n < NG) {
            int gate = n >> 9, h = n & 511;
            const float* W = (gate == 0) ? Wf : (gate == 1) ? Wi : (gate == 2) ? Wg : Wo;
            v = W[h * DH + d];
        } else {
            v = Wr[(n - NG) * DD + d];
        }
        g_Wx[i] = v;
    }
    for (int i = idx; i < NG * HH; i += stride) {
        int n = i / HH, k = i - n * HH;
        int gate = n >> 9, h = n & 511;
        const float* W = (gate == 0) ? Wf : (gate == 1) ? Wi : (gate == 2) ? Wg : Wo;
        g_Wh[i] = W[h * DH + DD + k];
    }
    for (int i = idx; i < NPRE; i += stride) {
        float v;
        if (i < NG) {
            int gate = i >> 9, h = i & 511;
            v = (gate == 0) ? bf[h] : (gate == 1) ? bi[h] : (gate == 2) ? bg[h] : bo[h];
        } else {
            v = br[i - NG];
        }
        g_bias[i] = v;
    }
}

// ---------------- batched input-side GEMM ----------------
// pre[t, n, b] = sum_d g_Wx[n,d] * x[t,b,d] + bias[n]
// tile 128 rows x 64 b, K=512; 128 threads, 8x8 microtile (1.0 MAC/B smem)
__global__ void __launch_bounds__(128) pre_gemm(const float* __restrict__ x) {
    const int t = blockIdx.y;
    const int nBase = blockIdx.x * 128;
    __shared__ float sW[16][128];
    __shared__ float sX[16][64];
    const int tid = threadIdx.x;
    const int rg = tid >> 3;          // 0..15 -> rows rg*8..+7
    const int bg = tid & 7;           // 0..7  -> b bg*8..+7
    const int xb = tid >> 1;          // 0..63
    const int xk = (tid & 1) * 8;
    const float* xt = x + (size_t)t * BB * DD;
    const float* wrow = &g_Wx[(size_t)(nBase + tid) * DD];

    float acc[8][8];
#pragma unroll
    for (int i = 0; i < 8; i++)
#pragma unroll
        for (int j = 0; j < 8; j++) acc[i][j] = 0.f;

    float4 pw0, pw1, pw2, pw3, px0, px1;
    pw0 = *(const float4*)(wrow + 0);
    pw1 = *(const float4*)(wrow + 4);
    pw2 = *(const float4*)(wrow + 8);
    pw3 = *(const float4*)(wrow + 12);
    {
        const float* xp = xt + (size_t)xb * DD + xk;
        px0 = *(const float4*)(xp);
        px1 = *(const float4*)(xp + 4);
    }

    for (int s = 0; s < 32; s++) {
        __syncthreads();   // WAR: previous compute done before overwrite
        sW[0][tid] = pw0.x;  sW[1][tid] = pw0.y;  sW[2][tid] = pw0.z;  sW[3][tid] = pw0.w;
        sW[4][tid] = pw1.x;  sW[5][tid] = pw1.y;  sW[6][tid] = pw1.z;  sW[7][tid] = pw1.w;
        sW[8][tid] = pw2.x;  sW[9][tid] = pw2.y;  sW[10][tid] = pw2.z; sW[11][tid] = pw2.w;
        sW[12][tid] = pw3.x; sW[13][tid] = pw3.y; sW[14][tid] = pw3.z; sW[15][tid] = pw3.w;
        sX[xk + 0][xb] = px0.x; sX[xk + 1][xb] = px0.y; sX[xk + 2][xb] = px0.z; sX[xk + 3][xb] = px0.w;
        sX[xk + 4][xb] = px1.x; sX[xk + 5][xb] = px1.y; sX[xk + 6][xb] = px1.z; sX[xk + 7][xb] = px1.w;
        __syncthreads();
        if (s < 31) {
            int kc = (s + 1) * 16;
            pw0 = *(const float4*)(wrow + kc + 0);
            pw1 = *(const float4*)(wrow + kc + 4);
            pw2 = *(const float4*)(wrow + kc + 8);
            pw3 = *(const float4*)(wrow + kc + 12);
            const float* xp = xt + (size_t)xb * DD + kc + xk;
            px0 = *(const float4*)(xp);
            px1 = *(const float4*)(xp + 4);
        }
#pragma unroll
        for (int k = 0; k < 16; k++) {
            float4 w0 = *(const float4*)&sW[k][rg * 8];
            float4 w1 = *(const float4*)&sW[k][rg * 8 + 4];
            float4 x0 = *(const float4*)&sX[k][bg * 8];
            float4 x1 = *(const float4*)&sX[k][bg * 8 + 4];
            float wv[8] = {w0.x, w0.y, w0.z, w0.w, w1.x, w1.y, w1.z, w1.w};
            float xv[8] = {x0.x, x0.y, x0.z, x0.w, x1.x, x1.y, x1.z, x1.w};
#pragma unroll
            for (int i = 0; i < 8; i++)
#pragma unroll
                for (int j = 0; j < 8; j++) acc[i][j] += wv[i] * xv[j];
        }
    }
    size_t base = (size_t)t * NPRE * BB;
#pragma unroll
    for (int i = 0; i < 8; i++) {
        int n = nBase + rg * 8 + i;
        float bv = g_bias[n];
        float4 o0, o1;
        o0.x = acc[i][0] + bv; o0.y = acc[i][1] + bv; o0.z = acc[i][2] + bv; o0.w = acc[i][3] + bv;
        o1.x = acc[i][4] + bv; o1.y = acc[i][5] + bv; o1.z = acc[i][6] + bv; o1.w = acc[i][7] + bv;
        *(float4*)&g_pre[base + (size_t)n * BB + bg * 8] = o0;
        *(float4*)&g_pre[base + (size_t)n * BB + bg * 8 + 4] = o1;
    }
}

// ---------------- grid-wide barrier (all NCTA CTAs co-resident) ----------------
__device__ __forceinline__ void grid_barrier() {
    __syncthreads();
    if (threadIdx.x == 0) {
        volatile unsigned* genp = &g_bar_gen;
        unsigned old = *genp;
        __threadfence();
        unsigned ticket = atomicAdd(&g_bar_count, 1);
        if (ticket == NCTA - 1) {
            g_bar_count = 0;
            __threadfence();
            atomicAdd(&g_bar_gen, 1);
        } else {
            while (*genp == old) { }
        }
    }
    __syncthreads();
}

// ---------------- persistent LSTM recurrence ----------------
// Phase A (t>0): CTA (cb,kb): 64 gate rows (4 gates x 16 cols) x 64 b, K slice 128.
//   8x4 microtile, partials -> g_part[kb][n][b].
// Phase B: CTA (cb2,bblk): 16 cols x 16 b cell updates; cell state in registers.
__global__ void __launch_bounds__(128) lstm_persistent(float* __restrict__ out) {
    const int tid = threadIdx.x;
    const int cta = blockIdx.x;
    const int cb = cta & 31;          // col block (16 h-cols)
    const int kb = cta >> 5;          // K block (128 k)
    const int jc = cb * 16;
    const int k0 = kb * 128;

    // GEMM microtile map
    const int rgrp = tid >> 4;        // 0..7  -> local rows rgrp*8..+7
    const int bgrp = tid & 15;        // 0..15 -> b bgrp*4..+3
    // stage-load map
    const int lrow = tid >> 1;        // 0..63
    const int lk = (tid & 1) * 8;
    const int n_l = (lrow >> 4) * 512 + jc + (lrow & 15);
    const float* wbase = &g_Wh[(size_t)n_l * HH + k0 + lk];
    // phase B map
    const int cb2 = cta >> 2;         // 0..31
    const int bblk = cta & 3;         // 0..3

    __shared__ float sW[16][64];
    __shared__ float sH[16][64];

    float c0 = 0.f, c1 = 0.f;         // register-resident cell state

    for (int t = 0; t < TT; t++) {
        if (t > 0) {
            const float* hbase = out + (size_t)(t - 1) * BB * HH + (size_t)lrow * HH + k0 + lk;
            float acc[8][4];
#pragma unroll
            for (int i = 0; i < 8; i++)
#pragma unroll
                for (int j = 0; j < 4; j++) acc[i][j] = 0.f;

            float4 pwA = *(const float4*)(wbase);
            float4 pwB = *(const float4*)(wbase + 4);
            float4 phA = *(const float4*)(hbase);
            float4 phB = *(const float4*)(hbase + 4);

            for (int s = 0; s < 8; s++) {
                __syncthreads();
                sW[lk + 0][lrow] = pwA.x; sW[lk + 1][lrow] = pwA.y;
                sW[lk + 2][lrow] = pwA.z; sW[lk + 3][lrow] = pwA.w;
                sW[lk + 4][lrow] = pwB.x; sW[lk + 5][lrow] = pwB.y;
                sW[lk + 6][lrow] = pwB.z; sW[lk + 7][lrow] = pwB.w;
                sH[lk + 0][lrow] = phA.x; sH[lk + 1][lrow] = phA.y;
                sH[lk + 2][lrow] = phA.z; sH[lk + 3][lrow] = phA.w;
                sH[lk + 4][lrow] = phB.x; sH[lk + 5][lrow] = phB.y;
                sH[lk + 6][lrow] = phB.z; sH[lk + 7][lrow] = phB.w;
                __syncthreads();
                if (s < 7) {
                    int kc = (s + 1) * 16;
                    pwA = *(const float4*)(wbase + kc);
                    pwB = *(const float4*)(wbase + kc + 4);
                    phA = *(const float4*)(hbase + kc);
                    phB = *(const float4*)(hbase + kc + 4);
                }
#pragma unroll
                for (int k = 0; k < 16; k++) {
                    float4 w0 = *(const float4*)&sW[k][rgrp * 8];
                    float4 w1 = *(const float4*)&sW[k][rgrp * 8 + 4];
                    float4 hv = *(const float4*)&sH[k][bgrp * 4];
                    float wv[8] = {w0.x, w0.y, w0.z, w0.w, w1.x, w1.y, w1.z, w1.w};
                    float hvv[4] = {hv.x, hv.y, hv.z, hv.w};
#pragma unroll
                    for (int i = 0; i < 8; i++)
#pragma unroll
                        for (int j = 0; j < 4; j++) acc[i][j] += wv[i] * hvv[j];
                }
            }
            // write partials
            float* pb = &g_part[(size_t)kb * NG * BB];
#pragma unroll
            for (int i = 0; i < 8; i++) {
                int r = rgrp * 8 + i;
                int n = (r >> 4) * 512 + jc + (r & 15);
                float4 o;
                o.x = acc[i][0]; o.y = acc[i][1]; o.z = acc[i][2]; o.w = acc[i][3];
                *(float4*)&pb[(size_t)n * BB + bgrp * 4] = o;
            }
            grid_barrier();
        }

        // ---- phase B: cell update ----
        const size_t preBase = (size_t)t * NPRE * BB;
#pragma unroll
        for (int u = 0; u < 2; u++) {
            int idx = tid + u * 128;
            int col = idx >> 4;
            int b = bblk * 16 + (idx & 15);
            int n0 = cb2 * 16 + col;
            float fp = g_pre[preBase + (size_t)n0 * BB + b];
            float ip = g_pre[preBase + (size_t)(512 + n0) * BB + b];
            float gp = g_pre[preBase + (size_t)(1024 + n0) * BB + b];
            float op = g_pre[preBase + (size_t)(1536 + n0) * BB + b];
            float rv = g_pre[preBase + (size_t)(2048 + n0) * BB + b];
            if (t > 0) {
#pragma unroll
                for (int p = 0; p < 4; p++) {
                    const float* pb2 = &g_part[(size_t)p * NG * BB];
                    fp += __ldcg(&pb2[(size_t)n0 * BB + b]);
                    ip += __ldcg(&pb2[(size_t)(512 + n0) * BB + b]);
                    gp += __ldcg(&pb2[(size_t)(1024 + n0) * BB + b]);
                    op += __ldcg(&pb2[(size_t)(1536 + n0) * BB + b]);
                }
            }
            float f = 1.f / (1.f + expf(-fp));
            float ii = 1.f / (1.f + expf(-ip));
            float gg = tanhf(gp);
            float oo = 1.f / (1.f + expf(-op));
            float cc = (u == 0) ? c0 : c1;
            cc = f * cc + ii * gg;
            if (u == 0) c0 = cc; else c1 = cc;
            out[(size_t)t * BB * HH + (size_t)b * HH + n0] = oo * tanhf(cc) + rv;
        }
        grid_barrier();
    }

    // ---- tail: publish cell state, then append (hx, cx) ----
#pragma unroll
    for (int u = 0; u < 2; u++) {
        int idx = tid + u * 128;
        int col = idx >> 4;
        int b = bblk * 16 + (idx & 15);
        int n0 = cb2 * 16 + col;
        g_c[(size_t)b * HH + n0] = (u == 0) ? c0 : c1;
    }
    grid_barrier();
    for (int i = cta * 128 + tid; i < BB * HH; i += NCTA * 128) {
        out[(size_t)TT * BB * HH + i] = __ldcg(&out[(size_t)(TT - 1) * BB * HH + i]);
        out[(size_t)TT * BB * HH + BB * HH + i] = __ldcg(&g_c[i]);
    }
}

extern "C" void kernel_launch(void* const* d_in, const int* in_sizes, int n_in,
                              void* d_out, int out_size) {
    const float* x  = (const float*)d_in[0];
    const float* Wf = (const float*)d_in[1];
    const float* bf = (const float*)d_in[2];
    const float* Wi = (const float*)d_in[3];
    const float* bi = (const float*)d_in[4];
    const float* Wg = (const float*)d_in[5];
    const float* bg = (const float*)d_in[6];
    const float* Wo = (const float*)d_in[7];
    const float* bo = (const float*)d_in[8];
    const float* Wr = (const float*)d_in[9];
    const float* br = (const float*)d_in[10];
    float* out = (float*)d_out;

    pack_kernel<<<256, 256>>>(Wf, bf, Wi, bi, Wg, bg, Wo, bo, Wr, br);
    pre_gemm<<<dim3(NPRE / 128, TT), 128>>>(x);
    lstm_persistent<<<NCTA, 128>>>(out);
}

// round 5
// speedup vs baseline: 2.5980x; 1.8155x over previous
#include <cuda_runtime.h>
#include <cuda_bf16.h>
#include <math.h>
#include <stdint.h>

#define TT 512
#define BB 64
#define DD 512
#define HH 512
#define DH 1024
#define NG 2048          // 4*H gate rows (packed: row = hcol*4 + gate)
#define NPRE 2560        // gates + residual rows (residual: 2048 + hcol)
#define NCTA 128
#define NTB (TT * BB)    // 32768 GEMM columns

// ---------------- scratch (device globals; no allocations) ----------------
__device__ __nv_bfloat16 g_Wxhi[(size_t)NPRE * DD];
__device__ __nv_bfloat16 g_Wxlo[(size_t)NPRE * DD];
__device__ __nv_bfloat16 g_Whhi[(size_t)NG * HH];
__device__ __nv_bfloat16 g_Whlo[(size_t)NG * HH];
__device__ __nv_bfloat16 g_xhi[(size_t)NTB * DD];
__device__ __nv_bfloat16 g_xlo[(size_t)NTB * DD];
__device__ float g_bias[NPRE];
__device__ float g_pre[(size_t)NTB * NPRE];      // [col = t*64+b][packed_n]
__device__ __nv_bfloat16 g_hhi[BB * HH];         // h state, bf16 hi/lo
__device__ __nv_bfloat16 g_hlo[BB * HH];
__device__ unsigned g_bar_count;
__device__ unsigned g_bar_gen;

// ---------------- mma / ldmatrix helpers (baseline PTX, sm_80+) ----------------
__device__ __forceinline__ uint32_t smem_u32(const void* p) {
    uint32_t a;
    asm("{ .reg .u64 t; cvta.to.shared.u64 t, %1; cvt.u32.u64 %0, t; }" : "=r"(a) : "l"(p));
    return a;
}
__device__ __forceinline__ void ldsm4(uint32_t addr, uint32_t* r) {
    asm volatile("ldmatrix.sync.aligned.m8n8.x4.shared.b16 {%0,%1,%2,%3}, [%4];"
                 : "=r"(r[0]), "=r"(r[1]), "=r"(r[2]), "=r"(r[3]) : "r"(addr));
}
__device__ __forceinline__ void ldsm2(uint32_t addr, uint32_t* r) {
    asm volatile("ldmatrix.sync.aligned.m8n8.x2.shared.b16 {%0,%1}, [%2];"
                 : "=r"(r[0]), "=r"(r[1]) : "r"(addr));
}
__device__ __forceinline__ void mma16816(float* d, const uint32_t* a, const uint32_t* b) {
    asm volatile("mma.sync.aligned.m16n8k16.row.col.f32.bf16.bf16.f32 "
                 "{%0,%1,%2,%3}, {%4,%5,%6,%7}, {%8,%9}, {%0,%1,%2,%3};"
                 : "+f"(d[0]), "+f"(d[1]), "+f"(d[2]), "+f"(d[3])
                 : "r"(a[0]), "r"(a[1]), "r"(a[2]), "r"(a[3]), "r"(b[0]), "r"(b[1]));
}

// ---------------- pack weights (gate-interleaved packed rows) ----------------
__global__ void pack_kernel(const float* __restrict__ Wf, const float* __restrict__ bf,
                            const float* __restrict__ Wi, const float* __restrict__ bi,
                            const float* __restrict__ Wg, const float* __restrict__ bg,
                            const float* __restrict__ Wo, const float* __restrict__ bo,
                            const float* __restrict__ Wr, const float* __restrict__ br) {
    int idx = blockIdx.x * blockDim.x + threadIdx.x;
    int stride = gridDim.x * blockDim.x;
    for (int i = idx; i < NPRE * DD; i += stride) {
        int n = i / DD, d = i - n * DD;
        float v;
        if (n < NG) {
            int hcol = n >> 2, gate = n & 3;
            const float* W = (gate == 0) ? Wf : (gate == 1) ? Wi : (gate == 2) ? Wg : Wo;
            v = W[hcol * DH + d];
        } else {
            v = Wr[(n - NG) * DD + d];
        }
        __nv_bfloat16 hi = __float2bfloat16_rn(v);
        g_Wxhi[i] = hi;
        g_Wxlo[i] = __float2bfloat16_rn(v - __bfloat162float(hi));
    }
    for (int i = idx; i < NG * HH; i += stride) {
        int n = i / HH, k = i - n * HH;
        int hcol = n >> 2, gate = n & 3;
        const float* W = (gate == 0) ? Wf : (gate == 1) ? Wi : (gate == 2) ? Wg : Wo;
        float v = W[hcol * DH + DD + k];
        __nv_bfloat16 hi = __float2bfloat16_rn(v);
        g_Whhi[i] = hi;
        g_Whlo[i] = __float2bfloat16_rn(v - __bfloat162float(hi));
    }
    for (int i = idx; i < NPRE; i += stride) {
        float v;
        if (i < NG) {
            int hcol = i >> 2, gate = i & 3;
            v = (gate == 0) ? bf[hcol] : (gate == 1) ? bi[hcol] : (gate == 2) ? bg[hcol] : bo[hcol];
        } else {
            v = br[i - NG];
        }
        g_bias[i] = v;
    }
}

// ---------------- x -> bf16 hi/lo ----------------
__global__ void xcvt_kernel(const float* __restrict__ x) {
    int idx = blockIdx.x * blockDim.x + threadIdx.x;
    int stride = gridDim.x * blockDim.x;
    for (size_t i = idx; i < (size_t)NTB * DD; i += stride) {
        float v = x[i];
        __nv_bfloat16 hi = __float2bfloat16_rn(v);
        g_xhi[i] = hi;
        g_xlo[i] = __float2bfloat16_rn(v - __bfloat162float(hi));
    }
}

// ---------------- pre-activation GEMM (HMMA, split bf16) ----------------
// D[m=2560 packed][n=32768 cols] = W * X^T + bias. CTA tile 128x128, 512 threads.
// smem stage: [buf][Ahi,Alo,Bhi,Blo] 128 rows x 32 k (padded to 40) bf16.
#define P_ROW 40                         // padded row (bf16 elems) -> 80B stride
#define P_HALF (128 * P_ROW * 2)         // 10240 B per operand-half per stage
#define P_STAGE (4 * P_HALF)             // 40960 B
#define P_SMEM (2 * P_STAGE)             // 81920 B
__global__ void __launch_bounds__(512) pre_gemm_mma() {
    extern __shared__ char sm[];
    const uint32_t smb = smem_u32(sm);
    const int tid = threadIdx.x;
    const int wid = tid >> 5, lane = tid & 31;
    const int mw = wid & 3, nw = wid >> 2;          // warp tile: m32 x n32
    const int mbase = blockIdx.x * 128;             // 20 m-tiles
    const int nbase = blockIdx.y * 128;             // 256 n-tiles

    // global loader mapping: operand-half o (0..3), row r (0..127), 64B per chunk
    const int o = tid >> 7, r = tid & 127;
    const __nv_bfloat16* gsrc =
        (o == 0) ? g_Wxhi + (size_t)(mbase + r) * DD :
        (o == 1) ? g_Wxlo + (size_t)(mbase + r) * DD :
        (o == 2) ? g_xhi + (size_t)(nbase + r) * DD :
                   g_xlo + (size_t)(nbase + r) * DD;
    const uint32_t sdst = smb + o * P_HALF + r * 80;

    // ldmatrix per-lane address offsets (within a half, byte units)
    const int aRow = mw * 32 + ((lane >> 3) & 1) * 8 + (lane & 7);
    const uint32_t aOff = (uint32_t)(aRow * 80 + ((lane >> 4) * 8) * 2);
    const int g8 = lane >> 3;
    uint32_t bOff[2];
#pragma unroll
    for (int pair = 0; pair < 2; pair++) {
        int nRow = nw * 32 + (pair * 2 + (g8 >> 1)) * 8 + (lane & 7);
        bOff[pair] = (uint32_t)(nRow * 80 + ((g8 & 1) * 8) * 2);
    }

    float acc[2][4][4];
#pragma unroll
    for (int i = 0; i < 2; i++)
#pragma unroll
        for (int j = 0; j < 4; j++)
#pragma unroll
            for (int q = 0; q < 4; q++) acc[i][j][q] = 0.f;

    uint4 pf[4];
    auto gload = [&](int chunk) {
        const __nv_bfloat16* p = gsrc + chunk * 32;
#pragma unroll
        for (int j = 0; j < 4; j++) pf[j] = *(const uint4*)(p + j * 8);
    };
    auto sstore = [&](int buf) {
        uint32_t d = sdst + buf * P_STAGE;
#pragma unroll
        for (int j = 0; j < 4; j++)
            *(uint4*)(sm + (d - smb) + j * 16) = pf[j];
    };
    auto do_mma = [&](int buf) {
        uint32_t base = smb + buf * P_STAGE;
#pragma unroll
        for (int kt = 0; kt < 2; kt++) {
            uint32_t ko = kt * 32;
            uint32_t aHi[2][4], aLo[2][4], bHi[4][2], bLo[4][2];
#pragma unroll
            for (int mt = 0; mt < 2; mt++) {
                ldsm4(base + 0 * P_HALF + aOff + mt * 16 * 80 + ko, aHi[mt]);
                ldsm4(base + 1 * P_HALF + aOff + mt * 16 * 80 + ko, aLo[mt]);
            }
#pragma unroll
            for (int pair = 0; pair < 2; pair++) {
                uint32_t t4[4];
                ldsm4(base + 2 * P_HALF + bOff[pair] + ko, t4);
                bHi[pair * 2][0] = t4[0]; bHi[pair * 2][1] = t4[1];
                bHi[pair * 2 + 1][0] = t4[2]; bHi[pair * 2 + 1][1] = t4[3];
                ldsm4(base + 3 * P_HALF + bOff[pair] + ko, t4);
                bLo[pair * 2][0] = t4[0]; bLo[pair * 2][1] = t4[1];
                bLo[pair * 2 + 1][0] = t4[2]; bLo[pair * 2 + 1][1] = t4[3];
            }
#pragma unroll
            for (int mt = 0; mt < 2; mt++)
#pragma unroll
                for (int nt = 0; nt < 4; nt++) {
                    mma16816(acc[mt][nt], aHi[mt], bHi[nt]);
                    mma16816(acc[mt][nt], aHi[mt], bLo[nt]);
                    mma16816(acc[mt][nt], aLo[mt], bHi[nt]);
                }
        }
    };

    gload(0); sstore(0);
    gload(1);
    __syncthreads();
    for (int c = 0; c < 16; c++) {
        do_mma(c & 1);
        if (c + 1 < 16) {
            __syncthreads();
            sstore((c + 1) & 1);
            if (c + 2 < 16) gload(c + 2);
            __syncthreads();
        }
    }
    __syncthreads();

    // epilogue: acc -> smem [c 128][pad 132] fp32, then coalesced +bias store
    float* smf = (float*)sm;
#pragma unroll
    for (int mt = 0; mt < 2; mt++)
#pragma unroll
        for (int nt = 0; nt < 4; nt++) {
            int c0 = nw * 32 + nt * 8 + 2 * (lane & 3);
            int r0 = mw * 32 + mt * 16 + (lane >> 2);
            smf[c0 * 132 + r0] = acc[mt][nt][0];
            smf[(c0 + 1) * 132 + r0] = acc[mt][nt][1];
            smf[c0 * 132 + r0 + 8] = acc[mt][nt][2];
            smf[(c0 + 1) * 132 + r0 + 8] = acc[mt][nt][3];
        }
    __syncthreads();
#pragma unroll
    for (int j = 0; j < 8; j++) {
        int idx = j * 512 + tid;
        int c = idx >> 5, seg = idx & 31;
        float4 v = *(const float4*)(smf + c * 132 + seg * 4);
        float4 bv = *(const float4*)&g_bias[mbase + seg * 4];
        v.x += bv.x; v.y += bv.y; v.z += bv.z; v.w += bv.w;
        *(float4*)&g_pre[(size_t)(nbase + c) * NPRE + mbase + seg * 4] = v;
    }
}

// ---------------- grid-wide barrier ----------------
__device__ __forceinline__ void grid_barrier() {
    __syncthreads();
    if (threadIdx.x == 0) {
        volatile unsigned* genp = &g_bar_gen;
        unsigned old = *genp;
        __threadfence();
        unsigned ticket = atomicAdd(&g_bar_count, 1);
        if (ticket == NCTA - 1) {
            g_bar_count = 0;
            __threadfence();
            atomicAdd(&g_bar_gen, 1);
        } else {
            while (*genp == old) { }
        }
    }
    __syncthreads();
}

// ---------------- persistent LSTM recurrence (HMMA, W resident in smem) ----------------
// 128 CTAs = 32 row-blocks (64 packed rows = 16 hcols) x 4 b-blocks (16 b).
// smem: Whi/Wlo [64][520], Bhi/Blo [16][520], sAcc [8 warps][16][8].
#define R_WROW 520                       // padded k (bf16) -> 1040B stride
#define R_OWHI 0
#define R_OWLO (64 * R_WROW * 2)         // 66560
#define R_OBHI (2 * 64 * R_WROW * 2)     // 133120
#define R_OBLO (R_OBHI + 16 * R_WROW * 2)
#define R_OACC (R_OBHI + 2 * 16 * R_WROW * 2)
#define R_SMEM (R_OACC + 8 * 16 * 8 * 4)
__global__ void __launch_bounds__(256) lstm_persistent(float* __restrict__ out) {
    extern __shared__ char sm[];
    const uint32_t smb = smem_u32(sm);
    const int tid = threadIdx.x;
    const int wid = tid >> 5, lane = tid & 31;
    const int cta = blockIdx.x;
    const int rb = cta & 31;             // 16 hcols: rb*16..
    const int bblk = cta >> 5;           // 16 b: bblk*16..
    const int mw = wid & 3;              // m16 tile within 64 rows
    const int nw = wid >> 2;             // b8 tile within 16 b

    // ---- load resident W slice (packed rows rb*64..+63), FULL k range ----
    for (int i = tid; i < 64 * 64 * 2; i += 256) {
        int hf = i >> 12;                // 0: hi, 1: lo  (64 rows * 64 chunks)
        int rem = i & 4095;
        int r = rem >> 6, s = rem & 63;
        const __nv_bfloat16* src = (hf ? g_Whlo : g_Whhi) + (size_t)(rb * 64 + r) * HH + s * 8;
        *(uint4*)(sm + (hf ? R_OWLO : R_OWHI) + r * (R_WROW * 2) + s * 16) = *(const uint4*)src;
    }

    // ldmatrix lane offsets
    const int aRow = mw * 16 + ((lane >> 3) & 1) * 8 + (lane & 7);
    const uint32_t aOff = (uint32_t)(aRow * (R_WROW * 2) + ((lane >> 4) * 8) * 2);
    const int l16 = lane & 15;
    const int bRow = nw * 8 + (l16 & 7);
    const uint32_t bOff = (uint32_t)(bRow * (R_WROW * 2) + (((l16 >> 3) & 1) * 8) * 2);

    // phase-B lane mapping: (hcol, b) pair owned across all steps
    const int hc_l = lane >> 3;          // 0..3
    const int b_l = lane & 7;            // 0..7
    const int hcol = rb * 16 + mw * 4 + hc_l;
    const int b = bblk * 16 + nw * 8 + b_l;
    float* sAccW = (float*)(sm + R_OACC) + wid * 128;

    float cst = 0.f;                     // cell state (register, one (hcol,b) per lane)
    float hlast = 0.f;

    __syncthreads();

    for (int t = 0; t < TT; t++) {
        float gv0 = 0.f, gv1 = 0.f, gv2 = 0.f, gv3 = 0.f;
        if (t > 0) {
            // stage h slice (16 b x 512 k, hi/lo) via L2 — FULL k range
            for (int i = tid; i < 16 * 64 * 2; i += 256) {
                int hf = i >> 10;        // 16 rows * 64 chunks
                int rem = i & 1023;
                int r = rem >> 6, s = rem & 63;
                const int4* src = (const int4*)((hf ? g_hlo : g_hhi) +
                                                (size_t)(bblk * 16 + r) * HH + s * 8);
                *(int4*)(sm + (hf ? R_OBLO : R_OBHI) + r * (R_WROW * 2) + s * 16) = __ldcg(src);
            }
            __syncthreads();

            float acc[4] = {0.f, 0.f, 0.f, 0.f};
#pragma unroll 4
            for (int kt = 0; kt < 32; kt++) {
                uint32_t ko = kt * 32;
                uint32_t aHi[4], aLo[4], bHi[2], bLo[2];
                ldsm4(smb + R_OWHI + aOff + ko, aHi);
                ldsm4(smb + R_OWLO + aOff + ko, aLo);
                ldsm2(smb + R_OBHI + bOff + ko, bHi);
                ldsm2(smb + R_OBLO + bOff + ko, bLo);
                mma16816(acc, aHi, bHi);
                mma16816(acc, aHi, bLo);
                mma16816(acc, aLo, bHi);
            }
            // park warp tile in smem, remap lanes to (hcol, b)
            {
                int r0 = lane >> 2, c0 = 2 * (lane & 3);
                sAccW[r0 * 8 + c0] = acc[0];
                sAccW[r0 * 8 + c0 + 1] = acc[1];
                sAccW[(r0 + 8) * 8 + c0] = acc[2];
                sAccW[(r0 + 8) * 8 + c0 + 1] = acc[3];
            }
            __syncwarp();
            gv0 = sAccW[(hc_l * 4 + 0) * 8 + b_l];
            gv1 = sAccW[(hc_l * 4 + 1) * 8 + b_l];
            gv2 = sAccW[(hc_l * 4 + 2) * 8 + b_l];
            gv3 = sAccW[(hc_l * 4 + 3) * 8 + b_l];
        }

        // cell update
        const size_t colBase = (size_t)(t * BB + b) * NPRE;
        float4 pg = *(const float4*)&g_pre[colBase + hcol * 4];
        float rv = g_pre[colBase + NG + hcol];
        float fp = pg.x + gv0, ip = pg.y + gv1, gp = pg.z + gv2, op = pg.w + gv3;
        float f = 1.f / (1.f + expf(-fp));
        float ii = 1.f / (1.f + expf(-ip));
        float gg = tanhf(gp);
        float oo = 1.f / (1.f + expf(-op));
        cst = f * cst + ii * gg;
        float h = oo * tanhf(cst) + rv;
        hlast = h;

        out[(size_t)t * BB * HH + (size_t)b * HH + hcol] = h;
        __nv_bfloat16 hhi = __float2bfloat16_rn(h);
        g_hhi[b * HH + hcol] = hhi;
        g_hlo[b * HH + hcol] = __float2bfloat16_rn(h - __bfloat162float(hhi));

        grid_barrier();   // h visible to all CTAs before next step's stage
    }

    // tail: (hx, cx) appended after stacked outputs
    out[(size_t)TT * BB * HH + (size_t)b * HH + hcol] = hlast;
    out[(size_t)TT * BB * HH + BB * HH + (size_t)b * HH + hcol] = cst;
}

extern "C" void kernel_launch(void* const* d_in, const int* in_sizes, int n_in,
                              void* d_out, int out_size) {
    const float* x  = (const float*)d_in[0];
    const float* Wf = (const float*)d_in[1];
    const float* bf = (const float*)d_in[2];
    const float* Wi = (const float*)d_in[3];
    const float* bi = (const float*)d_in[4];
    const float* Wg = (const float*)d_in[5];
    const float* bg = (const float*)d_in[6];
    const float* Wo = (const float*)d_in[7];
    const float* bo = (const float*)d_in[8];
    const float* Wr = (const float*)d_in[9];
    const float* br = (const float*)d_in[10];
    float* out = (float*)d_out;

    static int inited = 0;
    if (!inited) {
        cudaFuncSetAttribute(pre_gemm_mma, cudaFuncAttributeMaxDynamicSharedMemorySize, P_SMEM);
        cudaFuncSetAttribute(lstm_persistent, cudaFuncAttributeMaxDynamicSharedMemorySize, R_SMEM);
        inited = 1;
    }

    pack_kernel<<<256, 256>>>(Wf, bf, Wi, bi, Wg, bg, Wo, bo, Wr, br);
    xcvt_kernel<<<512, 256>>>(x);
    pre_gemm_mma<<<dim3(NPRE / 128, NTB / 128), 512, P_SMEM>>>();
    lstm_persistent<<<NCTA, 256, R_SMEM>>>(out);
}

// round 6
// speedup vs baseline: 2.7398x; 1.0546x over previous
#include <cuda_runtime.h>
#include <cuda_bf16.h>
#include <math.h>
#include <stdint.h>

#define TT 512
#define BB 64
#define DD 512
#define HH 512
#define DH 1024
#define NG 2048          // 4*H gate rows (packed: row = hcol*4 + gate)
#define NPRE 2560        // gates + residual rows (residual: 2048 + hcol)
#define NCTA 128
#define NTB (TT * BB)    // 32768 GEMM columns

// ---------------- scratch (device globals; no allocations) ----------------
__device__ __nv_bfloat16 g_Wxhi[(size_t)NPRE * DD];
__device__ __nv_bfloat16 g_Wxlo[(size_t)NPRE * DD];
__device__ __nv_bfloat16 g_Whhi[(size_t)NG * HH];
__device__ __nv_bfloat16 g_Whlo[(size_t)NG * HH];
__device__ __nv_bfloat16 g_xhi[(size_t)NTB * DD];
__device__ __nv_bfloat16 g_xlo[(size_t)NTB * DD];
__device__ float g_bias[NPRE];
__device__ float g_pre[(size_t)NTB * NPRE];      // [col = t*64+b][packed_n]
__device__ __nv_bfloat16 g_hhi[BB * HH];         // h state, bf16 hi/lo
__device__ __nv_bfloat16 g_hlo[BB * HH];
__device__ unsigned g_barc[4 * 32];              // per-group barrier (padded 128B)
__device__ unsigned g_barg[4 * 32];

// ---------------- mma / ldmatrix helpers (baseline PTX, sm_80+) ----------------
__device__ __forceinline__ uint32_t smem_u32(const void* p) {
    uint32_t a;
    asm("{ .reg .u64 t; cvta.to.shared.u64 t, %1; cvt.u32.u64 %0, t; }" : "=r"(a) : "l"(p));
    return a;
}
__device__ __forceinline__ void ldsm4(uint32_t addr, uint32_t* r) {
    asm volatile("ldmatrix.sync.aligned.m8n8.x4.shared.b16 {%0,%1,%2,%3}, [%4];"
                 : "=r"(r[0]), "=r"(r[1]), "=r"(r[2]), "=r"(r[3]) : "r"(addr));
}
__device__ __forceinline__ void mma16816(float* d, const uint32_t* a, const uint32_t* b) {
    asm volatile("mma.sync.aligned.m16n8k16.row.col.f32.bf16.bf16.f32 "
                 "{%0,%1,%2,%3}, {%4,%5,%6,%7}, {%8,%9}, {%0,%1,%2,%3};"
                 : "+f"(d[0]), "+f"(d[1]), "+f"(d[2]), "+f"(d[3])
                 : "r"(a[0]), "r"(a[1]), "r"(a[2]), "r"(a[3]), "r"(b[0]), "r"(b[1]));
}

// ---------------- pack weights (gate-interleaved packed rows) ----------------
__global__ void pack_kernel(const float* __restrict__ Wf, const float* __restrict__ bf,
                            const float* __restrict__ Wi, const float* __restrict__ bi,
                            const float* __restrict__ Wg, const float* __restrict__ bg,
                            const float* __restrict__ Wo, const float* __restrict__ bo,
                            const float* __restrict__ Wr, const float* __restrict__ br) {
    int idx = blockIdx.x * blockDim.x + threadIdx.x;
    int stride = gridDim.x * blockDim.x;
    for (int i = idx; i < NPRE * DD; i += stride) {
        int n = i / DD, d = i - n * DD;
        float v;
        if (n < NG) {
            int hcol = n >> 2, gate = n & 3;
            const float* W = (gate == 0) ? Wf : (gate == 1) ? Wi : (gate == 2) ? Wg : Wo;
            v = W[hcol * DH + d];
        } else {
            v = Wr[(n - NG) * DD + d];
        }
        __nv_bfloat16 hi = __float2bfloat16_rn(v);
        g_Wxhi[i] = hi;
        g_Wxlo[i] = __float2bfloat16_rn(v - __bfloat162float(hi));
    }
    for (int i = idx; i < NG * HH; i += stride) {
        int n = i / HH, k = i - n * HH;
        int hcol = n >> 2, gate = n & 3;
        const float* W = (gate == 0) ? Wf : (gate == 1) ? Wi : (gate == 2) ? Wg : Wo;
        float v = W[hcol * DH + DD + k];
        __nv_bfloat16 hi = __float2bfloat16_rn(v);
        g_Whhi[i] = hi;
        g_Whlo[i] = __float2bfloat16_rn(v - __bfloat162float(hi));
    }
    for (int i = idx; i < NPRE; i += stride) {
        float v;
        if (i < NG) {
            int hcol = i >> 2, gate = i & 3;
            v = (gate == 0) ? bf[hcol] : (gate == 1) ? bi[hcol] : (gate == 2) ? bg[hcol] : bo[hcol];
        } else {
            v = br[i - NG];
        }
        g_bias[i] = v;
    }
}

// ---------------- x -> bf16 hi/lo ----------------
__global__ void xcvt_kernel(const float* __restrict__ x) {
    int idx = blockIdx.x * blockDim.x + threadIdx.x;
    int stride = gridDim.x * blockDim.x;
    for (size_t i = idx; i < (size_t)NTB * DD; i += stride) {
        float v = x[i];
        __nv_bfloat16 hi = __float2bfloat16_rn(v);
        g_xhi[i] = hi;
        g_xlo[i] = __float2bfloat16_rn(v - __bfloat162float(hi));
    }
}

// ---------------- pre-activation GEMM (HMMA, split bf16) ----------------
#define P_ROW 40                         // padded row (bf16 elems) -> 80B stride
#define P_HALF (128 * P_ROW * 2)         // 10240 B per operand-half per stage
#define P_STAGE (4 * P_HALF)             // 40960 B
#define P_SMEM (2 * P_STAGE)             // 81920 B
__global__ void __launch_bounds__(512) pre_gemm_mma() {
    extern __shared__ char sm[];
    const uint32_t smb = smem_u32(sm);
    const int tid = threadIdx.x;
    const int wid = tid >> 5, lane = tid & 31;
    const int mw = wid & 3, nw = wid >> 2;          // warp tile: m32 x n32
    const int mbase = blockIdx.x * 128;             // 20 m-tiles
    const int nbase = blockIdx.y * 128;             // 256 n-tiles

    const int o = tid >> 7, r = tid & 127;
    const __nv_bfloat16* gsrc =
        (o == 0) ? g_Wxhi + (size_t)(mbase + r) * DD :
        (o == 1) ? g_Wxlo + (size_t)(mbase + r) * DD :
        (o == 2) ? g_xhi + (size_t)(nbase + r) * DD :
                   g_xlo + (size_t)(nbase + r) * DD;
    const uint32_t sdst = smb + o * P_HALF + r * 80;

    const int aRow = mw * 32 + ((lane >> 3) & 1) * 8 + (lane & 7);
    const uint32_t aOff = (uint32_t)(aRow * 80 + ((lane >> 4) * 8) * 2);
    const int g8 = lane >> 3;
    uint32_t bOff[2];
#pragma unroll
    for (int pair = 0; pair < 2; pair++) {
        int nRow = nw * 32 + (pair * 2 + (g8 >> 1)) * 8 + (lane & 7);
        bOff[pair] = (uint32_t)(nRow * 80 + ((g8 & 1) * 8) * 2);
    }

    float acc[2][4][4];
#pragma unroll
    for (int i = 0; i < 2; i++)
#pragma unroll
        for (int j = 0; j < 4; j++)
#pragma unroll
            for (int q = 0; q < 4; q++) acc[i][j][q] = 0.f;

    uint4 pf[4];
    auto gload = [&](int chunk) {
        const __nv_bfloat16* p = gsrc + chunk * 32;
#pragma unroll
        for (int j = 0; j < 4; j++) pf[j] = *(const uint4*)(p + j * 8);
    };
    auto sstore = [&](int buf) {
        uint32_t d = sdst + buf * P_STAGE;
#pragma unroll
        for (int j = 0; j < 4; j++)
            *(uint4*)(sm + (d - smb) + j * 16) = pf[j];
    };
    auto do_mma = [&](int buf) {
        uint32_t base = smb + buf * P_STAGE;
#pragma unroll
        for (int kt = 0; kt < 2; kt++) {
            uint32_t ko = kt * 32;
            uint32_t aHi[2][4], aLo[2][4], bHi[4][2], bLo[4][2];
#pragma unroll
            for (int mt = 0; mt < 2; mt++) {
                ldsm4(base + 0 * P_HALF + aOff + mt * 16 * 80 + ko, aHi[mt]);
                ldsm4(base + 1 * P_HALF + aOff + mt * 16 * 80 + ko, aLo[mt]);
            }
#pragma unroll
            for (int pair = 0; pair < 2; pair++) {
                uint32_t t4[4];
                ldsm4(base + 2 * P_HALF + bOff[pair] + ko, t4);
                bHi[pair * 2][0] = t4[0]; bHi[pair * 2][1] = t4[1];
                bHi[pair * 2 + 1][0] = t4[2]; bHi[pair * 2 + 1][1] = t4[3];
                ldsm4(base + 3 * P_HALF + bOff[pair] + ko, t4);
                bLo[pair * 2][0] = t4[0]; bLo[pair * 2][1] = t4[1];
                bLo[pair * 2 + 1][0] = t4[2]; bLo[pair * 2 + 1][1] = t4[3];
            }
#pragma unroll
            for (int mt = 0; mt < 2; mt++)
#pragma unroll
                for (int nt = 0; nt < 4; nt++) {
                    mma16816(acc[mt][nt], aHi[mt], bHi[nt]);
                    mma16816(acc[mt][nt], aHi[mt], bLo[nt]);
                    mma16816(acc[mt][nt], aLo[mt], bHi[nt]);
                }
        }
    };

    gload(0); sstore(0);
    gload(1);
    __syncthreads();
    for (int c = 0; c < 16; c++) {
        do_mma(c & 1);
        if (c + 1 < 16) {
            __syncthreads();
            sstore((c + 1) & 1);
            if (c + 2 < 16) gload(c + 2);
            __syncthreads();
        }
    }
    __syncthreads();

    float* smf = (float*)sm;
#pragma unroll
    for (int mt = 0; mt < 2; mt++)
#pragma unroll
        for (int nt = 0; nt < 4; nt++) {
            int c0 = nw * 32 + nt * 8 + 2 * (lane & 3);
            int r0 = mw * 32 + mt * 16 + (lane >> 2);
            smf[c0 * 132 + r0] = acc[mt][nt][0];
            smf[(c0 + 1) * 132 + r0] = acc[mt][nt][1];
            smf[c0 * 132 + r0 + 8] = acc[mt][nt][2];
            smf[(c0 + 1) * 132 + r0 + 8] = acc[mt][nt][3];
        }
    __syncthreads();
#pragma unroll
    for (int j = 0; j < 8; j++) {
        int idx = j * 512 + tid;
        int c = idx >> 5, seg = idx & 31;
        float4 v = *(const float4*)(smf + c * 132 + seg * 4);
        float4 bv = *(const float4*)&g_bias[mbase + seg * 4];
        v.x += bv.x; v.y += bv.y; v.z += bv.z; v.w += bv.w;
        *(float4*)&g_pre[(size_t)(nbase + c) * NPRE + mbase + seg * 4] = v;
    }
}

// ---------------- per-group (32-CTA) barrier ----------------
__device__ __forceinline__ void group_barrier(int grp) {
    __syncthreads();
    if (threadIdx.x == 0) {
        volatile unsigned* genp = &g_barg[grp * 32];
        unsigned old = *genp;
        __threadfence();
        unsigned ticket = atomicAdd(&g_barc[grp * 32], 1);
        if (ticket == 31) {
            g_barc[grp * 32] = 0;
            __threadfence();
            atomicAdd((unsigned*)genp, 1);
        } else {
            while (*genp == old) { }
        }
    }
    __syncthreads();
}

// ---------------- persistent LSTM recurrence (HMMA, W resident in smem) ----------------
// 128 CTAs = 32 row-blocks (64 packed rows = 16 hcols) x 4 independent b-groups (16 b).
#define R_WROW 520                       // padded k (bf16) -> 1040B stride
#define R_OWHI 0
#define R_OWLO (64 * R_WROW * 2)         // 66560
#define R_OBHI (2 * 64 * R_WROW * 2)     // 133120
#define R_OBLO (R_OBHI + 16 * R_WROW * 2)
#define R_OACC (R_OBHI + 2 * 16 * R_WROW * 2)
#define R_SMEM (R_OACC + 8 * 16 * 8 * 4)
__global__ void __launch_bounds__(256) lstm_persistent(float* __restrict__ out) {
    extern __shared__ char sm[];
    const uint32_t smb = smem_u32(sm);
    const int tid = threadIdx.x;
    const int wid = tid >> 5, lane = tid & 31;
    const int cta = blockIdx.x;
    const int rb = cta & 31;             // 16 hcols: rb*16..
    const int bblk = cta >> 5;           // group: 16 b = bblk*16..
    const int mw = wid & 3;              // m16 tile within 64 rows
    const int nw = wid >> 2;             // b8 tile within 16 b

    // ---- load resident W slice (packed rows rb*64..+63), full k ----
    for (int i = tid; i < 64 * 64 * 2; i += 256) {
        int hf = i >> 12;
        int rem = i & 4095;
        int r = rem >> 6, s = rem & 63;
        const __nv_bfloat16* src = (hf ? g_Whlo : g_Whhi) + (size_t)(rb * 64 + r) * HH + s * 8;
        *(uint4*)(sm + (hf ? R_OWLO : R_OWHI) + r * (R_WROW * 2) + s * 16) = *(const uint4*)src;
    }

    // ldmatrix lane offsets
    const int aRow = mw * 16 + ((lane >> 3) & 1) * 8 + (lane & 7);
    const uint32_t aOff = (uint32_t)(aRow * (R_WROW * 2) + ((lane >> 4) * 8) * 2);
    const int bRow = nw * 8 + (lane & 7);            // ldsm4 over k32
    const uint32_t bOff = (uint32_t)(bRow * (R_WROW * 2) + ((lane >> 3) * 8) * 2);

    // phase-B lane mapping
    const int hc_l = lane >> 3;
    const int b_l = lane & 7;
    const int hcol = rb * 16 + mw * 4 + hc_l;
    const int b = bblk * 16 + nw * 8 + b_l;
    float* sAccW = (float*)(sm + R_OACC) + wid * 128;

    float cst = 0.f;
    float hlast = 0.f;

    // g_pre prefetch registers
    float4 pg;
    float rv;
    {
        const size_t cb = (size_t)(0 * BB + b) * NPRE;
        pg = __ldcs((const float4*)&g_pre[cb + hcol * 4]);
        rv = __ldcs(&g_pre[cb + NG + hcol]);
    }

    __syncthreads();

    for (int t = 0; t < TT; t++) {
        float gv0 = 0.f, gv1 = 0.f, gv2 = 0.f, gv3 = 0.f;
        if (t > 0) {
            // stage h slice (16 b x 512 k, hi/lo)
            for (int i = tid; i < 16 * 64 * 2; i += 256) {
                int hf = i >> 10;
                int rem = i & 1023;
                int r = rem >> 6, s = rem & 63;
                const int4* src = (const int4*)((hf ? g_hlo : g_hhi) +
                                                (size_t)(bblk * 16 + r) * HH + s * 8);
                *(int4*)(sm + (hf ? R_OBLO : R_OBHI) + r * (R_WROW * 2) + s * 16) = __ldcg(src);
            }
            __syncthreads();

            float acc[4] = {0.f, 0.f, 0.f, 0.f};
#pragma unroll 4
            for (int kt2 = 0; kt2 < 16; kt2++) {
                uint32_t ko = kt2 * 64;              // k32 per iteration (bytes)
                uint32_t aHi0[4], aHi1[4], aLo0[4], aLo1[4], bH[4], bL[4];
                ldsm4(smb + R_OWHI + aOff + ko, aHi0);
                ldsm4(smb + R_OWHI + aOff + ko + 32, aHi1);
                ldsm4(smb + R_OWLO + aOff + ko, aLo0);
                ldsm4(smb + R_OWLO + aOff + ko + 32, aLo1);
                ldsm4(smb + R_OBHI + bOff + ko, bH);
                ldsm4(smb + R_OBLO + bOff + ko, bL);
                mma16816(acc, aHi0, bH);
                mma16816(acc, aHi0, bL);
                mma16816(acc, aLo0, bH);
                mma16816(acc, aHi1, bH + 2);
                mma16816(acc, aHi1, bL + 2);
                mma16816(acc, aLo1, bH + 2);
            }
            {
                int r0 = lane >> 2, c0 = 2 * (lane & 3);
                sAccW[r0 * 8 + c0] = acc[0];
                sAccW[r0 * 8 + c0 + 1] = acc[1];
                sAccW[(r0 + 8) * 8 + c0] = acc[2];
                sAccW[(r0 + 8) * 8 + c0 + 1] = acc[3];
            }
            __syncwarp();
            gv0 = sAccW[(hc_l * 4 + 0) * 8 + b_l];
            gv1 = sAccW[(hc_l * 4 + 1) * 8 + b_l];
            gv2 = sAccW[(hc_l * 4 + 2) * 8 + b_l];
            gv3 = sAccW[(hc_l * 4 + 3) * 8 + b_l];
        }

        // cell update (g_pre values prefetched)
        float fp = pg.x + gv0, ip = pg.y + gv1, gp = pg.z + gv2, op = pg.w + gv3;
        float f = 1.f / (1.f + expf(-fp));
        float ii = 1.f / (1.f + expf(-ip));
        float gg = tanhf(gp);
        float oo = 1.f / (1.f + expf(-op));
        cst = f * cst + ii * gg;
        float h = oo * tanhf(cst) + rv;
        hlast = h;

        out[(size_t)t * BB * HH + (size_t)b * HH + hcol] = h;
        __nv_bfloat16 hhi = __float2bfloat16_rn(h);
        g_hhi[b * HH + hcol] = hhi;
        g_hlo[b * HH + hcol] = __float2bfloat16_rn(h - __bfloat162float(hhi));

        // prefetch g_pre for t+1 (hides behind the barrier)
        if (t + 1 < TT) {
            const size_t cb = (size_t)((t + 1) * BB + b) * NPRE;
            pg = __ldcs((const float4*)&g_pre[cb + hcol * 4]);
            rv = __ldcs(&g_pre[cb + NG + hcol]);
            group_barrier(bblk);
        }
    }

    // tail: (hx, cx) appended after stacked outputs
    out[(size_t)TT * BB * HH + (size_t)b * HH + hcol] = hlast;
    out[(size_t)TT * BB * HH + BB * HH + (size_t)b * HH + hcol] = cst;
}

extern "C" void kernel_launch(void* const* d_in, const int* in_sizes, int n_in,
                              void* d_out, int out_size) {
    const float* x  = (const float*)d_in[0];
    const float* Wf = (const float*)d_in[1];
    const float* bf = (const float*)d_in[2];
    const float* Wi = (const float*)d_in[3];
    const float* bi = (const float*)d_in[4];
    const float* Wg = (const float*)d_in[5];
    const float* bg = (const float*)d_in[6];
    const float* Wo = (const float*)d_in[7];
    const float* bo = (const float*)d_in[8];
    const float* Wr = (const float*)d_in[9];
    const float* br = (const float*)d_in[10];
    float* out = (float*)d_out;

    static int inited = 0;
    if (!inited) {
        cudaFuncSetAttribute(pre_gemm_mma, cudaFuncAttributeMaxDynamicSharedMemorySize, P_SMEM);
        cudaFuncSetAttribute(lstm_persistent, cudaFuncAttributeMaxDynamicSharedMemorySize, R_SMEM);
        inited = 1;
    }

    pack_kernel<<<256, 256>>>(Wf, bf, Wi, bi, Wg, bg, Wo, bo, Wr, br);
    xcvt_kernel<<<512, 256>>>(x);
    pre_gemm_mma<<<dim3(NPRE / 128, NTB / 128), 512, P_SMEM>>>();
    lstm_persistent<<<NCTA, 256, R_SMEM>>>(out);
}

// round 7
// speedup vs baseline: 2.8683x; 1.0469x over previous
#include <cuda_runtime.h>
#include <cuda_bf16.h>
#include <math.h>
#include <stdint.h>

#define TT 512
#define BB 64
#define DD 512
#define HH 512
#define DH 1024
#define NG 2048          // 4*H gate rows (packed: row = hcol*4 + gate)
#define NPRE 2560        // gates + residual rows (residual: 2048 + hcol)
#define NCTA 128
#define NTB (TT * BB)    // 32768 GEMM columns

// ---------------- scratch (device globals; no allocations) ----------------
__device__ __nv_bfloat16 g_Wxhi[(size_t)NPRE * DD];
__device__ __nv_bfloat16 g_Wxlo[(size_t)NPRE * DD];
__device__ __nv_bfloat16 g_Whhi[(size_t)NG * HH];
__device__ __nv_bfloat16 g_Whlo[(size_t)NG * HH];
__device__ __nv_bfloat16 g_xhi[(size_t)NTB * DD];
__device__ __nv_bfloat16 g_xlo[(size_t)NTB * DD];
__device__ float g_bias[NPRE];
__device__ float g_pre[(size_t)NTB * NPRE];      // [col = t*64+b][packed_n]
__device__ __nv_bfloat16 g_hhi[2 * BB * HH];     // h state, double-buffered
__device__ __nv_bfloat16 g_hlo[2 * BB * HH];
__device__ unsigned g_barc[4 * 32];              // per-group barrier (padded 128B)
__device__ unsigned g_barg[4 * 32];

// ---------------- mma / ldmatrix helpers (baseline PTX, sm_80+) ----------------
__device__ __forceinline__ uint32_t smem_u32(const void* p) {
    uint32_t a;
    asm("{ .reg .u64 t; cvta.to.shared.u64 t, %1; cvt.u32.u64 %0, t; }" : "=r"(a) : "l"(p));
    return a;
}
__device__ __forceinline__ void ldsm4(uint32_t addr, uint32_t* r) {
    asm volatile("ldmatrix.sync.aligned.m8n8.x4.shared.b16 {%0,%1,%2,%3}, [%4];"
                 : "=r"(r[0]), "=r"(r[1]), "=r"(r[2]), "=r"(r[3]) : "r"(addr));
}
__device__ __forceinline__ void mma16816(float* d, const uint32_t* a, const uint32_t* b) {
    asm volatile("mma.sync.aligned.m16n8k16.row.col.f32.bf16.bf16.f32 "
                 "{%0,%1,%2,%3}, {%4,%5,%6,%7}, {%8,%9}, {%0,%1,%2,%3};"
                 : "+f"(d[0]), "+f"(d[1]), "+f"(d[2]), "+f"(d[3])
                 : "r"(a[0]), "r"(a[1]), "r"(a[2]), "r"(a[3]), "r"(b[0]), "r"(b[1]));
}
__device__ __forceinline__ void st_cg_b16(__nv_bfloat16* p, __nv_bfloat16 v) {
    unsigned short u = *(unsigned short*)&v;
    asm volatile("st.global.cg.u16 [%0], %1;" :: "l"(p), "h"(u) : "memory");
}

// ---------------- pack weights (gate-interleaved packed rows) ----------------
__global__ void pack_kernel(const float* __restrict__ Wf, const float* __restrict__ bf,
                            const float* __restrict__ Wi, const float* __restrict__ bi,
                            const float* __restrict__ Wg, const float* __restrict__ bg,
                            const float* __restrict__ Wo, const float* __restrict__ bo,
                            const float* __restrict__ Wr, const float* __restrict__ br) {
    int idx = blockIdx.x * blockDim.x + threadIdx.x;
    int stride = gridDim.x * blockDim.x;
    for (int i = idx; i < NPRE * DD; i += stride) {
        int n = i / DD, d = i - n * DD;
        float v;
        if (n < NG) {
            int hcol = n >> 2, gate = n & 3;
            const float* W = (gate == 0) ? Wf : (gate == 1) ? Wi : (gate == 2) ? Wg : Wo;
            v = W[hcol * DH + d];
        } else {
            v = Wr[(n - NG) * DD + d];
        }
        __nv_bfloat16 hi = __float2bfloat16_rn(v);
        g_Wxhi[i] = hi;
        g_Wxlo[i] = __float2bfloat16_rn(v - __bfloat162float(hi));
    }
    for (int i = idx; i < NG * HH; i += stride) {
        int n = i / HH, k = i - n * HH;
        int hcol = n >> 2, gate = n & 3;
        const float* W = (gate == 0) ? Wf : (gate == 1) ? Wi : (gate == 2) ? Wg : Wo;
        float v = W[hcol * DH + DD + k];
        __nv_bfloat16 hi = __float2bfloat16_rn(v);
        g_Whhi[i] = hi;
        g_Whlo[i] = __float2bfloat16_rn(v - __bfloat162float(hi));
    }
    for (int i = idx; i < NPRE; i += stride) {
        float v;
        if (i < NG) {
            int hcol = i >> 2, gate = i & 3;
            v = (gate == 0) ? bf[hcol] : (gate == 1) ? bi[hcol] : (gate == 2) ? bg[hcol] : bo[hcol];
        } else {
            v = br[i - NG];
        }
        g_bias[i] = v;
    }
}

// ---------------- x -> bf16 hi/lo ----------------
__global__ void xcvt_kernel(const float* __restrict__ x) {
    int idx = blockIdx.x * blockDim.x + threadIdx.x;
    int stride = gridDim.x * blockDim.x;
    for (size_t i = idx; i < (size_t)NTB * DD; i += stride) {
        float v = x[i];
        __nv_bfloat16 hi = __float2bfloat16_rn(v);
        g_xhi[i] = hi;
        g_xlo[i] = __float2bfloat16_rn(v - __bfloat162float(hi));
    }
}

// ---------------- pre-activation GEMM (HMMA, split bf16) ----------------
#define P_ROW 40                         // padded row (bf16 elems) -> 80B stride
#define P_HALF (128 * P_ROW * 2)         // 10240 B per operand-half per stage
#define P_STAGE (4 * P_HALF)             // 40960 B
#define P_SMEM (2 * P_STAGE)             // 81920 B
__global__ void __launch_bounds__(512) pre_gemm_mma() {
    extern __shared__ char sm[];
    const uint32_t smb = smem_u32(sm);
    const int tid = threadIdx.x;
    const int wid = tid >> 5, lane = tid & 31;
    const int mw = wid & 3, nw = wid >> 2;          // warp tile: m32 x n32
    const int mbase = blockIdx.x * 128;             // 20 m-tiles
    const int nbase = blockIdx.y * 128;             // 256 n-tiles

    const int o = tid >> 7, r = tid & 127;
    const __nv_bfloat16* gsrc =
        (o == 0) ? g_Wxhi + (size_t)(mbase + r) * DD :
        (o == 1) ? g_Wxlo + (size_t)(mbase + r) * DD :
        (o == 2) ? g_xhi + (size_t)(nbase + r) * DD :
                   g_xlo + (size_t)(nbase + r) * DD;
    const uint32_t sdst = smb + o * P_HALF + r * 80;

    const int aRow = mw * 32 + ((lane >> 3) & 1) * 8 + (lane & 7);
    const uint32_t aOff = (uint32_t)(aRow * 80 + ((lane >> 4) * 8) * 2);
    const int g8 = lane >> 3;
    uint32_t bOff[2];
#pragma unroll
    for (int pair = 0; pair < 2; pair++) {
        int nRow = nw * 32 + (pair * 2 + (g8 >> 1)) * 8 + (lane & 7);
        bOff[pair] = (uint32_t)(nRow * 80 + ((g8 & 1) * 8) * 2);
    }

    float acc[2][4][4];
#pragma unroll
    for (int i = 0; i < 2; i++)
#pragma unroll
        for (int j = 0; j < 4; j++)
#pragma unroll
            for (int q = 0; q < 4; q++) acc[i][j][q] = 0.f;

    uint4 pf[4];
    auto gload = [&](int chunk) {
        const __nv_bfloat16* p = gsrc + chunk * 32;
#pragma unroll
        for (int j = 0; j < 4; j++) pf[j] = *(const uint4*)(p + j * 8);
    };
    auto sstore = [&](int buf) {
        uint32_t d = sdst + buf * P_STAGE;
#pragma unroll
        for (int j = 0; j < 4; j++)
            *(uint4*)(sm + (d - smb) + j * 16) = pf[j];
    };
    auto do_mma = [&](int buf) {
        uint32_t base = smb + buf * P_STAGE;
#pragma unroll
        for (int kt = 0; kt < 2; kt++) {
            uint32_t ko = kt * 32;
            uint32_t aHi[2][4], aLo[2][4], bHi[4][2], bLo[4][2];
#pragma unroll
            for (int mt = 0; mt < 2; mt++) {
                ldsm4(base + 0 * P_HALF + aOff + mt * 16 * 80 + ko, aHi[mt]);
                ldsm4(base + 1 * P_HALF + aOff + mt * 16 * 80 + ko, aLo[mt]);
            }
#pragma unroll
            for (int pair = 0; pair < 2; pair++) {
                uint32_t t4[4];
                ldsm4(base + 2 * P_HALF + bOff[pair] + ko, t4);
                bHi[pair * 2][0] = t4[0]; bHi[pair * 2][1] = t4[1];
                bHi[pair * 2 + 1][0] = t4[2]; bHi[pair * 2 + 1][1] = t4[3];
                ldsm4(base + 3 * P_HALF + bOff[pair] + ko, t4);
                bLo[pair * 2][0] = t4[0]; bLo[pair * 2][1] = t4[1];
                bLo[pair * 2 + 1][0] = t4[2]; bLo[pair * 2 + 1][1] = t4[3];
            }
#pragma unroll
            for (int mt = 0; mt < 2; mt++)
#pragma unroll
                for (int nt = 0; nt < 4; nt++) {
                    mma16816(acc[mt][nt], aHi[mt], bHi[nt]);
                    mma16816(acc[mt][nt], aHi[mt], bLo[nt]);
                    mma16816(acc[mt][nt], aLo[mt], bHi[nt]);
                }
        }
    };

    gload(0); sstore(0);
    gload(1);
    __syncthreads();
    for (int c = 0; c < 16; c++) {
        do_mma(c & 1);
        if (c + 1 < 16) {
            __syncthreads();
            sstore((c + 1) & 1);
            if (c + 2 < 16) gload(c + 2);
            __syncthreads();
        }
    }
    __syncthreads();

    float* smf = (float*)sm;
#pragma unroll
    for (int mt = 0; mt < 2; mt++)
#pragma unroll
        for (int nt = 0; nt < 4; nt++) {
            int c0 = nw * 32 + nt * 8 + 2 * (lane & 3);
            int r0 = mw * 32 + mt * 16 + (lane >> 2);
            smf[c0 * 132 + r0] = acc[mt][nt][0];
            smf[(c0 + 1) * 132 + r0] = acc[mt][nt][1];
            smf[c0 * 132 + r0 + 8] = acc[mt][nt][2];
            smf[(c0 + 1) * 132 + r0 + 8] = acc[mt][nt][3];
        }
    __syncthreads();
#pragma unroll
    for (int j = 0; j < 8; j++) {
        int idx = j * 512 + tid;
        int c = idx >> 5, seg = idx & 31;
        float4 v = *(const float4*)(smf + c * 132 + seg * 4);
        float4 bv = *(const float4*)&g_bias[mbase + seg * 4];
        v.x += bv.x; v.y += bv.y; v.z += bv.z; v.w += bv.w;
        *(float4*)&g_pre[(size_t)(nbase + c) * NPRE + mbase + seg * 4] = v;
    }
}

// ---------------- acquire/release group barrier (no L1-flushing fences) ----------------
__device__ __forceinline__ unsigned bar_arrive(int grp) {
    __syncthreads();                      // order all threads' h stores before release
    unsigned old = 0;
    if (threadIdx.x == 0) {
        asm volatile("ld.relaxed.gpu.global.u32 %0, [%1];"
                     : "=r"(old) : "l"(&g_barg[grp * 32]));
        unsigned ticket;
        asm volatile("atom.release.gpu.global.add.u32 %0, [%1], 1;"
                     : "=r"(ticket) : "l"(&g_barc[grp * 32]) : "memory");
        if (ticket == 31) {
            asm volatile("st.relaxed.gpu.global.u32 [%0], %1;"
                         :: "l"(&g_barc[grp * 32]), "r"(0u) : "memory");
            asm volatile("red.release.gpu.global.add.u32 [%0], 1;"
                         :: "l"(&g_barg[grp * 32]) : "memory");
        }
    }
    return old;                           // valid in thread 0 only
}
__device__ __forceinline__ void bar_wait(int grp, unsigned old) {
    if (threadIdx.x == 0) {
        unsigned v;
        do {
            asm volatile("ld.acquire.gpu.global.u32 %0, [%1];"
                         : "=r"(v) : "l"(&g_barg[grp * 32]) : "memory");
        } while (v == old);
    }
    __syncthreads();
}

// ---------------- persistent LSTM recurrence (HMMA, W resident in smem) ----------------
// 128 CTAs = 32 row-blocks (64 packed rows = 16 hcols) x 4 independent b-groups (16 b).
#define R_WROW 520                       // padded k (bf16) -> 1040B stride
#define R_OWHI 0
#define R_OWLO (64 * R_WROW * 2)         // 66560
#define R_OBHI (2 * 64 * R_WROW * 2)     // 133120
#define R_OBLO (R_OBHI + 16 * R_WROW * 2)
#define R_OACC (R_OBHI + 2 * 16 * R_WROW * 2)
#define R_SMEM (R_OACC + 8 * 16 * 8 * 4)
__global__ void __launch_bounds__(256) lstm_persistent(float* __restrict__ out) {
    extern __shared__ char sm[];
    const uint32_t smb = smem_u32(sm);
    const int tid = threadIdx.x;
    const int wid = tid >> 5, lane = tid & 31;
    const int cta = blockIdx.x;
    const int rb = cta & 31;             // 16 hcols: rb*16..
    const int bblk = cta >> 5;           // group: 16 b = bblk*16..
    const int mw = wid & 3;              // m16 tile within 64 rows
    const int nw = wid >> 2;             // b8 tile within 16 b

    // ---- load resident W slice (packed rows rb*64..+63), full k ----
    for (int i = tid; i < 64 * 64 * 2; i += 256) {
        int hf = i >> 12;
        int rem = i & 4095;
        int r = rem >> 6, s = rem & 63;
        const __nv_bfloat16* src = (hf ? g_Whlo : g_Whhi) + (size_t)(rb * 64 + r) * HH + s * 8;
        *(uint4*)(sm + (hf ? R_OWLO : R_OWHI) + r * (R_WROW * 2) + s * 16) = *(const uint4*)src;
    }

    // ldmatrix lane offsets
    const int aRow = mw * 16 + ((lane >> 3) & 1) * 8 + (lane & 7);
    const uint32_t aOff = (uint32_t)(aRow * (R_WROW * 2) + ((lane >> 4) * 8) * 2);
    const int bRow = nw * 8 + (lane & 7);            // ldsm4 over k32
    const uint32_t bOff = (uint32_t)(bRow * (R_WROW * 2) + ((lane >> 3) * 8) * 2);

    // phase-B lane mapping
    const int hc_l = lane >> 3;
    const int b_l = lane & 7;
    const int hcol = rb * 16 + mw * 4 + hc_l;
    const int b = bblk * 16 + nw * 8 + b_l;
    float* sAccW = (float*)(sm + R_OACC) + wid * 128;

    float cst = 0.f;
    float hlast = 0.f;
    unsigned bold = 0;

    // g_pre prefetch registers
    float4 pg;
    float rv;
    {
        const size_t cb = (size_t)(0 * BB + b) * NPRE;
        pg = __ldcs((const float4*)&g_pre[cb + hcol * 4]);
        rv = __ldcs(&g_pre[cb + NG + hcol]);
    }

    __syncthreads();

    for (int t = 0; t < TT; t++) {
        float gv0 = 0.f, gv1 = 0.f, gv2 = 0.f, gv3 = 0.f;
        if (t > 0) {
            bar_wait(bblk, bold);        // h_{t-1} published by whole group
            const int rbuf = (t - 1) & 1;
            // stage h slice (16 b x 512 k, hi/lo) from read buffer
            for (int i = tid; i < 16 * 64 * 2; i += 256) {
                int hf = i >> 10;
                int rem = i & 1023;
                int r = rem >> 6, s = rem & 63;
                const int4* src = (const int4*)((hf ? g_hlo : g_hhi) + rbuf * BB * HH +
                                                (size_t)(bblk * 16 + r) * HH + s * 8);
                *(int4*)(sm + (hf ? R_OBLO : R_OBHI) + r * (R_WROW * 2) + s * 16) = __ldcg(src);
            }
            __syncthreads();

            float acc[4] = {0.f, 0.f, 0.f, 0.f};
#pragma unroll 4
            for (int kt2 = 0; kt2 < 16; kt2++) {
                uint32_t ko = kt2 * 64;              // k32 per iteration (bytes)
                uint32_t aHi0[4], aHi1[4], aLo0[4], aLo1[4], bH[4], bL[4];
                ldsm4(smb + R_OWHI + aOff + ko, aHi0);
                ldsm4(smb + R_OWHI + aOff + ko + 32, aHi1);
                ldsm4(smb + R_OWLO + aOff + ko, aLo0);
                ldsm4(smb + R_OWLO + aOff + ko + 32, aLo1);
                ldsm4(smb + R_OBHI + bOff + ko, bH);
                ldsm4(smb + R_OBLO + bOff + ko, bL);
                mma16816(acc, aHi0, bH);
                mma16816(acc, aHi0, bL);
                mma16816(acc, aLo0, bH);
                mma16816(acc, aHi1, bH + 2);
                mma16816(acc, aHi1, bL + 2);
                mma16816(acc, aLo1, bH + 2);
            }
            {
                int r0 = lane >> 2, c0 = 2 * (lane & 3);
                sAccW[r0 * 8 + c0] = acc[0];
                sAccW[r0 * 8 + c0 + 1] = acc[1];
                sAccW[(r0 + 8) * 8 + c0] = acc[2];
                sAccW[(r0 + 8) * 8 + c0 + 1] = acc[3];
            }
            __syncwarp();
            gv0 = sAccW[(hc_l * 4 + 0) * 8 + b_l];
            gv1 = sAccW[(hc_l * 4 + 1) * 8 + b_l];
            gv2 = sAccW[(hc_l * 4 + 2) * 8 + b_l];
            gv3 = sAccW[(hc_l * 4 + 3) * 8 + b_l];
        }

        // cell update (g_pre values prefetched)
        float fp = pg.x + gv0, ip = pg.y + gv1, gp = pg.z + gv2, op = pg.w + gv3;
        float f = 1.f / (1.f + expf(-fp));
        float ii = 1.f / (1.f + expf(-ip));
        float gg = tanhf(gp);
        float oo = 1.f / (1.f + expf(-op));
        cst = f * cst + ii * gg;
        float h = oo * tanhf(cst) + rv;
        hlast = h;

        // publish h to write buffer (L2-direct), then arrive
        const int wbuf = t & 1;
        __nv_bfloat16 hhi = __float2bfloat16_rn(h);
        st_cg_b16(&g_hhi[wbuf * BB * HH + b * HH + hcol], hhi);
        st_cg_b16(&g_hlo[wbuf * BB * HH + b * HH + hcol],
                  __float2bfloat16_rn(h - __bfloat162float(hhi)));

        if (t + 1 < TT) {
            bold = bar_arrive(bblk);
            // off-critical-path work between arrive and next wait:
            out[(size_t)t * BB * HH + (size_t)b * HH + hcol] = h;
            const size_t cb = (size_t)((t + 1) * BB + b) * NPRE;
            pg = __ldcs((const float4*)&g_pre[cb + hcol * 4]);
            rv = __ldcs(&g_pre[cb + NG + hcol]);
        } else {
            out[(size_t)t * BB * HH + (size_t)b * HH + hcol] = h;
        }
    }

    // tail: (hx, cx) appended after stacked outputs
    out[(size_t)TT * BB * HH + (size_t)b * HH + hcol] = hlast;
    out[(size_t)TT * BB * HH + BB * HH + (size_t)b * HH + hcol] = cst;
}

extern "C" void kernel_launch(void* const* d_in, const int* in_sizes, int n_in,
                              void* d_out, int out_size) {
    const float* x  = (const float*)d_in[0];
    const float* Wf = (const float*)d_in[1];
    const float* bf = (const float*)d_in[2];
    const float* Wi = (const float*)d_in[3];
    const float* bi = (const float*)d_in[4];
    const float* Wg = (const float*)d_in[5];
    const float* bg = (const float*)d_in[6];
    const float* Wo = (const float*)d_in[7];
    const float* bo = (const float*)d_in[8];
    const float* Wr = (const float*)d_in[9];
    const float* br = (const float*)d_in[10];
    float* out = (float*)d_out;

    static int inited = 0;
    if (!inited) {
        cudaFuncSetAttribute(pre_gemm_mma, cudaFuncAttributeMaxDynamicSharedMemorySize, P_SMEM);
        cudaFuncSetAttribute(lstm_persistent, cudaFuncAttributeMaxDynamicSharedMemorySize, R_SMEM);
        inited = 1;
    }

    pack_kernel<<<256, 256>>>(Wf, bf, Wi, bi, Wg, bg, Wo, bo, Wr, br);
    xcvt_kernel<<<512, 256>>>(x);
    pre_gemm_mma<<<dim3(NPRE / 128, NTB / 128), 512, P_SMEM>>>();
    lstm_persistent<<<NCTA, 256, R_SMEM>>>(out);
}

// round 8
// speedup vs baseline: 3.1630x; 1.1027x over previous
#include <cuda_runtime.h>
#include <cuda_bf16.h>
#include <math.h>
#include <stdint.h>

#define TT 512
#define BB 64
#define DD 512
#define HH 512
#define DH 1024
#define NG 2048          // 4*H gate rows (packed: row = hcol*4 + gate)
#define NPRE 2560        // gates + residual rows (residual: 2048 + hcol)
#define NCTA 128
#define NTB (TT * BB)    // 32768 GEMM columns

// ---------------- scratch (device globals; no allocations) ----------------
__device__ __nv_bfloat16 g_Wxhi[(size_t)NPRE * DD];
__device__ __nv_bfloat16 g_Wxlo[(size_t)NPRE * DD];
__device__ __nv_bfloat16 g_Whhi[(size_t)NG * HH];
__device__ __nv_bfloat16 g_Whlo[(size_t)NG * HH];
__device__ __nv_bfloat16 g_xhi[(size_t)NTB * DD];
__device__ __nv_bfloat16 g_xlo[(size_t)NTB * DD];
__device__ float g_bias[NPRE];
__device__ float g_pre[(size_t)NTB * NPRE];      // [col = t*64+b][packed_n]
__device__ __nv_bfloat16 g_hhi[2 * BB * HH];     // h state, double-buffered
__device__ __nv_bfloat16 g_hlo[2 * BB * HH];
__device__ unsigned g_barc[4 * 32];              // per-group barrier (padded 128B)
__device__ unsigned g_barg[4 * 32];

// ---------------- mma / ldmatrix helpers (baseline PTX, sm_80+) ----------------
__device__ __forceinline__ uint32_t smem_u32(const void* p) {
    uint32_t a;
    asm("{ .reg .u64 t; cvta.to.shared.u64 t, %1; cvt.u32.u64 %0, t; }" : "=r"(a) : "l"(p));
    return a;
}
__device__ __forceinline__ void ldsm4(uint32_t addr, uint32_t* r) {
    asm volatile("ldmatrix.sync.aligned.m8n8.x4.shared.b16 {%0,%1,%2,%3}, [%4];"
                 : "=r"(r[0]), "=r"(r[1]), "=r"(r[2]), "=r"(r[3]) : "r"(addr));
}
__device__ __forceinline__ void mma16816(float* d, const uint32_t* a, const uint32_t* b) {
    asm volatile("mma.sync.aligned.m16n8k16.row.col.f32.bf16.bf16.f32 "
                 "{%0,%1,%2,%3}, {%4,%5,%6,%7}, {%8,%9}, {%0,%1,%2,%3};"
                 : "+f"(d[0]), "+f"(d[1]), "+f"(d[2]), "+f"(d[3])
                 : "r"(a[0]), "r"(a[1]), "r"(a[2]), "r"(a[3]), "r"(b[0]), "r"(b[1]));
}
__device__ __forceinline__ void st_cg_b16(__nv_bfloat16* p, __nv_bfloat16 v) {
    unsigned short u = *(unsigned short*)&v;
    asm volatile("st.global.cg.u16 [%0], %1;" :: "l"(p), "h"(u) : "memory");
}
__device__ __forceinline__ void cp_async16(uint32_t dst, const void* src) {
    asm volatile("cp.async.cg.shared.global [%0], [%1], 16;" :: "r"(dst), "l"(src) : "memory");
}

// ---------------- pack weights (gate-interleaved packed rows) ----------------
__global__ void pack_kernel(const float* __restrict__ Wf, const float* __restrict__ bf,
                            const float* __restrict__ Wi, const float* __restrict__ bi,
                            const float* __restrict__ Wg, const float* __restrict__ bg,
                            const float* __restrict__ Wo, const float* __restrict__ bo,
                            const float* __restrict__ Wr, const float* __restrict__ br) {
    int idx = blockIdx.x * blockDim.x + threadIdx.x;
    int stride = gridDim.x * blockDim.x;
    for (int i = idx; i < NPRE * DD; i += stride) {
        int n = i / DD, d = i - n * DD;
        float v;
        if (n < NG) {
            int hcol = n >> 2, gate = n & 3;
            const float* W = (gate == 0) ? Wf : (gate == 1) ? Wi : (gate == 2) ? Wg : Wo;
            v = W[hcol * DH + d];
        } else {
            v = Wr[(n - NG) * DD + d];
        }
        __nv_bfloat16 hi = __float2bfloat16_rn(v);
        g_Wxhi[i] = hi;
        g_Wxlo[i] = __float2bfloat16_rn(v - __bfloat162float(hi));
    }
    for (int i = idx; i < NG * HH; i += stride) {
        int n = i / HH, k = i - n * HH;
        int hcol = n >> 2, gate = n & 3;
        const float* W = (gate == 0) ? Wf : (gate == 1) ? Wi : (gate == 2) ? Wg : Wo;
        float v = W[hcol * DH + DD + k];
        __nv_bfloat16 hi = __float2bfloat16_rn(v);
        g_Whhi[i] = hi;
        g_Whlo[i] = __float2bfloat16_rn(v - __bfloat162float(hi));
    }
    for (int i = idx; i < NPRE; i += stride) {
        float v;
        if (i < NG) {
            int hcol = i >> 2, gate = i & 3;
            v = (gate == 0) ? bf[hcol] : (gate == 1) ? bi[hcol] : (gate == 2) ? bg[hcol] : bo[hcol];
        } else {
            v = br[i - NG];
        }
        g_bias[i] = v;
    }
}

// ---------------- x -> bf16 hi/lo ----------------
__global__ void xcvt_kernel(const float* __restrict__ x) {
    int idx = blockIdx.x * blockDim.x + threadIdx.x;
    int stride = gridDim.x * blockDim.x;
    for (size_t i = idx; i < (size_t)NTB * DD; i += stride) {
        float v = x[i];
        __nv_bfloat16 hi = __float2bfloat16_rn(v);
        g_xhi[i] = hi;
        g_xlo[i] = __float2bfloat16_rn(v - __bfloat162float(hi));
    }
}

// ---------------- pre-activation GEMM (HMMA, split bf16) ----------------
#define P_ROW 40                         // padded row (bf16 elems) -> 80B stride
#define P_HALF (128 * P_ROW * 2)         // 10240 B per operand-half per stage
#define P_STAGE (4 * P_HALF)             // 40960 B
#define P_SMEM (2 * P_STAGE)             // 81920 B
__global__ void __launch_bounds__(512) pre_gemm_mma() {
    extern __shared__ char sm[];
    const uint32_t smb = smem_u32(sm);
    const int tid = threadIdx.x;
    const int wid = tid >> 5, lane = tid & 31;
    const int mw = wid & 3, nw = wid >> 2;          // warp tile: m32 x n32
    const int mbase = blockIdx.x * 128;             // 20 m-tiles
    const int nbase = blockIdx.y * 128;             // 256 n-tiles

    const int o = tid >> 7, r = tid & 127;
    const __nv_bfloat16* gsrc =
        (o == 0) ? g_Wxhi + (size_t)(mbase + r) * DD :
        (o == 1) ? g_Wxlo + (size_t)(mbase + r) * DD :
        (o == 2) ? g_xhi + (size_t)(nbase + r) * DD :
                   g_xlo + (size_t)(nbase + r) * DD;
    const uint32_t sdst = smb + o * P_HALF + r * 80;

    const int aRow = mw * 32 + ((lane >> 3) & 1) * 8 + (lane & 7);
    const uint32_t aOff = (uint32_t)(aRow * 80 + ((lane >> 4) * 8) * 2);
    const int g8 = lane >> 3;
    uint32_t bOff[2];
#pragma unroll
    for (int pair = 0; pair < 2; pair++) {
        int nRow = nw * 32 + (pair * 2 + (g8 >> 1)) * 8 + (lane & 7);
        bOff[pair] = (uint32_t)(nRow * 80 + ((g8 & 1) * 8) * 2);
    }

    float acc[2][4][4];
#pragma unroll
    for (int i = 0; i < 2; i++)
#pragma unroll
        for (int j = 0; j < 4; j++)
#pragma unroll
            for (int q = 0; q < 4; q++) acc[i][j][q] = 0.f;

    uint4 pf[4];
    auto gload = [&](int chunk) {
        const __nv_bfloat16* p = gsrc + chunk * 32;
#pragma unroll
        for (int j = 0; j < 4; j++) pf[j] = *(const uint4*)(p + j * 8);
    };
    auto sstore = [&](int buf) {
        uint32_t d = sdst + buf * P_STAGE;
#pragma unroll
        for (int j = 0; j < 4; j++)
            *(uint4*)(sm + (d - smb) + j * 16) = pf[j];
    };
    auto do_mma = [&](int buf) {
        uint32_t base = smb + buf * P_STAGE;
#pragma unroll
        for (int kt = 0; kt < 2; kt++) {
            uint32_t ko = kt * 32;
            uint32_t aHi[2][4], aLo[2][4], bHi[4][2], bLo[4][2];
#pragma unroll
            for (int mt = 0; mt < 2; mt++) {
                ldsm4(base + 0 * P_HALF + aOff + mt * 16 * 80 + ko, aHi[mt]);
                ldsm4(base + 1 * P_HALF + aOff + mt * 16 * 80 + ko, aLo[mt]);
            }
#pragma unroll
            for (int pair = 0; pair < 2; pair++) {
                uint32_t t4[4];
                ldsm4(base + 2 * P_HALF + bOff[pair] + ko, t4);
                bHi[pair * 2][0] = t4[0]; bHi[pair * 2][1] = t4[1];
                bHi[pair * 2 + 1][0] = t4[2]; bHi[pair * 2 + 1][1] = t4[3];
                ldsm4(base + 3 * P_HALF + bOff[pair] + ko, t4);
                bLo[pair * 2][0] = t4[0]; bLo[pair * 2][1] = t4[1];
                bLo[pair * 2 + 1][0] = t4[2]; bLo[pair * 2 + 1][1] = t4[3];
            }
#pragma unroll
            for (int mt = 0; mt < 2; mt++)
#pragma unroll
                for (int nt = 0; nt < 4; nt++) {
                    mma16816(acc[mt][nt], aHi[mt], bHi[nt]);
                    mma16816(acc[mt][nt], aHi[mt], bLo[nt]);
                    mma16816(acc[mt][nt], aLo[mt], bHi[nt]);
                }
        }
    };

    // single-sync-per-chunk double buffering: chunk c lives in buf c&1
    gload(0); sstore(0);
    gload(1);
    __syncthreads();
    for (int c = 0; c < 16; c++) {
        if (c + 1 < 16) sstore((c + 1) & 1);   // pf holds chunk c+1
        if (c + 2 < 16) gload(c + 2);
        do_mma(c & 1);
        __syncthreads();
    }

    float* smf = (float*)sm;
#pragma unroll
    for (int mt = 0; mt < 2; mt++)
#pragma unroll
        for (int nt = 0; nt < 4; nt++) {
            int c0 = nw * 32 + nt * 8 + 2 * (lane & 3);
            int r0 = mw * 32 + mt * 16 + (lane >> 2);
            smf[c0 * 132 + r0] = acc[mt][nt][0];
            smf[(c0 + 1) * 132 + r0] = acc[mt][nt][1];
            smf[c0 * 132 + r0 + 8] = acc[mt][nt][2];
            smf[(c0 + 1) * 132 + r0 + 8] = acc[mt][nt][3];
        }
    __syncthreads();
#pragma unroll
    for (int j = 0; j < 8; j++) {
        int idx = j * 512 + tid;
        int c = idx >> 5, seg = idx & 31;
        float4 v = *(const float4*)(smf + c * 132 + seg * 4);
        float4 bv = *(const float4*)&g_bias[mbase + seg * 4];
        v.x += bv.x; v.y += bv.y; v.z += bv.z; v.w += bv.w;
        *(float4*)&g_pre[(size_t)(nbase + c) * NPRE + mbase + seg * 4] = v;
    }
}

// ---------------- acquire/release group barrier, all-thread polling ----------------
__device__ __forceinline__ unsigned bar_read_gen(int grp) {
    unsigned v;
    asm volatile("ld.relaxed.gpu.global.u32 %0, [%1];"
                 : "=r"(v) : "l"(&g_barg[grp * 32]));
    return v;
}
__device__ __forceinline__ void bar_arrive(int grp) {
    __syncthreads();                      // order all threads' h stores before release
    if (threadIdx.x == 0) {
        unsigned ticket;
        asm volatile("atom.acq_rel.gpu.global.add.u32 %0, [%1], 1;"
                     : "=r"(ticket) : "l"(&g_barc[grp * 32]) : "memory");
        if (ticket == 31) {
            asm volatile("st.relaxed.gpu.global.u32 [%0], %1;"
                         :: "l"(&g_barc[grp * 32]), "r"(0u) : "memory");
            asm volatile("red.release.gpu.global.add.u32 [%0], 1;"
                         :: "l"(&g_barg[grp * 32]) : "memory");
        }
    }
}
__device__ __forceinline__ void bar_wait_all(int grp, unsigned old) {
    unsigned v;
    do {
        asm volatile("ld.relaxed.gpu.global.u32 %0, [%1];"
                     : "=r"(v) : "l"(&g_barg[grp * 32]) : "memory");
    } while (v == old);
    asm volatile("ld.acquire.gpu.global.u32 %0, [%1];"
                 : "=r"(v) : "l"(&g_barg[grp * 32]) : "memory");
}

// ---------------- persistent LSTM recurrence (HMMA, W resident in smem) ----------------
// 128 CTAs = 32 row-blocks (64 packed rows = 16 hcols) x 4 independent b-groups (16 b).
#define R_WROW 520                       // padded k (bf16) -> 1040B stride
#define R_OWHI 0
#define R_OWLO (64 * R_WROW * 2)         // 66560
#define R_OBHI (2 * 64 * R_WROW * 2)     // 133120
#define R_OBLO (R_OBHI + 16 * R_WROW * 2)
#define R_OACC (R_OBHI + 2 * 16 * R_WROW * 2)
#define R_SMEM (R_OACC + 8 * 16 * 8 * 4)
__global__ void __launch_bounds__(256) lstm_persistent(float* __restrict__ out) {
    extern __shared__ char sm[];
    const uint32_t smb = smem_u32(sm);
    const int tid = threadIdx.x;
    const int wid = tid >> 5, lane = tid & 31;
    const int cta = blockIdx.x;
    const int rb = cta & 31;             // 16 hcols: rb*16..
    const int bblk = cta >> 5;           // group: 16 b = bblk*16..
    const int mw = wid & 3;              // m16 tile within 64 rows
    const int nw = wid >> 2;             // b8 tile within 16 b

    // ---- load resident W slice (packed rows rb*64..+63), full k ----
    for (int i = tid; i < 64 * 64 * 2; i += 256) {
        int hf = i >> 12;
        int rem = i & 4095;
        int r = rem >> 6, s = rem & 63;
        const __nv_bfloat16* src = (hf ? g_Whlo : g_Whhi) + (size_t)(rb * 64 + r) * HH + s * 8;
        *(uint4*)(sm + (hf ? R_OWLO : R_OWHI) + r * (R_WROW * 2) + s * 16) = *(const uint4*)src;
    }

    // ldmatrix lane offsets
    const int aRow = mw * 16 + ((lane >> 3) & 1) * 8 + (lane & 7);
    const uint32_t aOff = (uint32_t)(aRow * (R_WROW * 2) + ((lane >> 4) * 8) * 2);
    const int bRow = nw * 8 + (lane & 7);            // ldsm4 over k32
    const uint32_t bOff = (uint32_t)(bRow * (R_WROW * 2) + ((lane >> 3) * 8) * 2);

    // phase-B lane mapping
    const int hc_l = lane >> 3;
    const int b_l = lane & 7;
    const int hcol = rb * 16 + mw * 4 + hc_l;
    const int b = bblk * 16 + nw * 8 + b_l;
    float* sAccW = (float*)(sm + R_OACC) + wid * 128;

    float cst = 0.f;
    float hlast = 0.f;
    unsigned bold = 0;

    // g_pre prefetch registers
    float4 pg;
    float rv;
    {
        const size_t cb = (size_t)(0 * BB + b) * NPRE;
        pg = __ldcs((const float4*)&g_pre[cb + hcol * 4]);
        rv = __ldcs(&g_pre[cb + NG + hcol]);
    }

    __syncthreads();

    for (int t = 0; t < TT; t++) {
        float gv0 = 0.f, gv1 = 0.f, gv2 = 0.f, gv3 = 0.f;
        if (t > 0) {
            bar_wait_all(bblk, bold);    // every thread self-wakes; no trailing sync
            const int rbuf = (t - 1) & 1;
            // stage h slice (16 b x 512 k, hi/lo) via cp.async
            for (int i = tid; i < 16 * 64 * 2; i += 256) {
                int hf = i >> 10;
                int rem = i & 1023;
                int r = rem >> 6, s = rem & 63;
                const void* src = (const void*)((hf ? g_hlo : g_hhi) + rbuf * BB * HH +
                                                (size_t)(bblk * 16 + r) * HH + s * 8);
                cp_async16(smb + (hf ? R_OBLO : R_OBHI) + r * (R_WROW * 2) + s * 16, src);
            }
            asm volatile("cp.async.commit_group;" ::: "memory");
            asm volatile("cp.async.wait_group 0;" ::: "memory");
            __syncthreads();

            // six independent accumulator chains (3 products x 2 k-halves)
            float aA0[4] = {}, aB0[4] = {}, aC0[4] = {};
            float aA1[4] = {}, aB1[4] = {}, aC1[4] = {};
#pragma unroll 4
            for (int kt2 = 0; kt2 < 16; kt2++) {
                uint32_t ko = kt2 * 64;              // k32 per iteration (bytes)
                uint32_t aHi0[4], aHi1[4], aLo0[4], aLo1[4], bH[4], bL[4];
                ldsm4(smb + R_OWHI + aOff + ko, aHi0);
                ldsm4(smb + R_OWHI + aOff + ko + 32, aHi1);
                ldsm4(smb + R_OWLO + aOff + ko, aLo0);
                ldsm4(smb + R_OWLO + aOff + ko + 32, aLo1);
                ldsm4(smb + R_OBHI + bOff + ko, bH);
                ldsm4(smb + R_OBLO + bOff + ko, bL);
                mma16816(aA0, aHi0, bH);
                mma16816(aB0, aHi0, bL);
                mma16816(aC0, aLo0, bH);
                mma16816(aA1, aHi1, bH + 2);
                mma16816(aB1, aHi1, bL + 2);
                mma16816(aC1, aLo1, bH + 2);
            }
            {
                int r0 = lane >> 2, c0 = 2 * (lane & 3);
                sAccW[r0 * 8 + c0]           = aA0[0] + aB0[0] + aC0[0] + aA1[0] + aB1[0] + aC1[0];
                sAccW[r0 * 8 + c0 + 1]       = aA0[1] + aB0[1] + aC0[1] + aA1[1] + aB1[1] + aC1[1];
                sAccW[(r0 + 8) * 8 + c0]     = aA0[2] + aB0[2] + aC0[2] + aA1[2] + aB1[2] + aC1[2];
                sAccW[(r0 + 8) * 8 + c0 + 1] = aA0[3] + aB0[3] + aC0[3] + aA1[3] + aB1[3] + aC1[3];
            }
            __syncwarp();
            gv0 = sAccW[(hc_l * 4 + 0) * 8 + b_l];
            gv1 = sAccW[(hc_l * 4 + 1) * 8 + b_l];
            gv2 = sAccW[(hc_l * 4 + 2) * 8 + b_l];
            gv3 = sAccW[(hc_l * 4 + 3) * 8 + b_l];
        }

        // cell update (g_pre values prefetched)
        float fp = pg.x + gv0, ip = pg.y + gv1, gp = pg.z + gv2, op = pg.w + gv3;
        float f = 1.f / (1.f + expf(-fp));
        float ii = 1.f / (1.f + expf(-ip));
        float gg = tanhf(gp);
        float oo = 1.f / (1.f + expf(-op));
        cst = f * cst + ii * gg;
        float h = oo * tanhf(cst) + rv;
        hlast = h;

        // publish h to write buffer (L2-direct), then arrive
        const int wbuf = t & 1;
        __nv_bfloat16 hhi = __float2bfloat16_rn(h);
        st_cg_b16(&g_hhi[wbuf * BB * HH + b * HH + hcol], hhi);
        st_cg_b16(&g_hlo[wbuf * BB * HH + b * HH + hcol],
                  __float2bfloat16_rn(h - __bfloat162float(hhi)));

        if (t + 1 < TT) {
            bold = bar_read_gen(bblk);   // safe: gen can't advance until this CTA arrives
            bar_arrive(bblk);
            // off-critical-path work between arrive and next wait:
            out[(size_t)t * BB * HH + (size_t)b * HH + hcol] = h;
            const size_t cb = (size_t)((t + 1) * BB + b) * NPRE;
            pg = __ldcs((const float4*)&g_pre[cb + hcol * 4]);
            rv = __ldcs(&g_pre[cb + NG + hcol]);
        } else {
            out[(size_t)t * BB * HH + (size_t)b * HH + hcol] = h;
        }
    }

    // tail: (hx, cx) appended after stacked outputs
    out[(size_t)TT * BB * HH + (size_t)b * HH + hcol] = hlast;
    out[(size_t)TT * BB * HH + BB * HH + (size_t)b * HH + hcol] = cst;
}

extern "C" void kernel_launch(void* const* d_in, const int* in_sizes, int n_in,
                              void* d_out, int out_size) {
    const float* x  = (const float*)d_in[0];
    const float* Wf = (const float*)d_in[1];
    const float* bf = (const float*)d_in[2];
    const float* Wi = (const float*)d_in[3];
    const float* bi = (const float*)d_in[4];
    const float* Wg = (const float*)d_in[5];
    const float* bg = (const float*)d_in[6];
    const float* Wo = (const float*)d_in[7];
    const float* bo = (const float*)d_in[8];
    const float* Wr = (const float*)d_in[9];
    const float* br = (const float*)d_in[10];
    float* out = (float*)d_out;

    static int inited = 0;
    if (!inited) {
        cudaFuncSetAttribute(pre_gemm_mma, cudaFuncAttributeMaxDynamicSharedMemorySize, P_SMEM);
        cudaFuncSetAttribute(lstm_persistent, cudaFuncAttributeMaxDynamicSharedMemorySize, R_SMEM);
        inited = 1;
    }

    pack_kernel<<<256, 256>>>(Wf, bf, Wi, bi, Wg, bg, Wo, bo, Wr, br);
    xcvt_kernel<<<512, 256>>>(x);
    pre_gemm_mma<<<dim3(NPRE / 128, NTB / 128), 512, P_SMEM>>>();
    lstm_persistent<<<NCTA, 256, R_SMEM>>>(out);
}

// round 10
// speedup vs baseline: 3.3838x; 1.0698x over previous
#include <cuda_runtime.h>
#include <cuda_bf16.h>
#include <math.h>
#include <stdint.h>

#define TT 512
#define BB 64
#define DD 512
#define HH 512
#define DH 1024
#define NG 2048          // 4*H gate rows (packed: row = hcol*4 + gate)
#define NPRE 2560        // gates + residual rows (residual: 2048 + hcol)
#define NCTA 128
#define NTB (TT * BB)    // 32768 GEMM columns

// ---------------- scratch (device globals; no allocations) ----------------
__device__ __nv_bfloat16 g_Wxhi[(size_t)NPRE * DD];
__device__ __nv_bfloat16 g_Wxlo[(size_t)NPRE * DD];
__device__ __nv_bfloat16 g_Whhi[(size_t)NG * HH];
__device__ __nv_bfloat16 g_Whlo[(size_t)NG * HH];
__device__ __nv_bfloat16 g_xhi[(size_t)NTB * DD];
__device__ __nv_bfloat16 g_xlo[(size_t)NTB * DD];
__device__ float g_bias[NPRE];
__device__ float g_pre[(size_t)NTB * NPRE];      // [col = t*64+b][packed_n]
__device__ __nv_bfloat16 g_hhi[2 * BB * HH];     // h state, double-buffered
__device__ __nv_bfloat16 g_hlo[2 * BB * HH];
__device__ unsigned g_barc[4 * 32];              // per-group barrier (padded 128B)
__device__ unsigned g_barg[4 * 32];

// ---------------- mma / ldmatrix helpers (baseline PTX, sm_80+) ----------------
__device__ __forceinline__ uint32_t smem_u32(const void* p) {
    uint32_t a;
    asm("{ .reg .u64 t; cvta.to.shared.u64 t, %1; cvt.u32.u64 %0, t; }" : "=r"(a) : "l"(p));
    return a;
}
__device__ __forceinline__ void ldsm4(uint32_t addr, uint32_t* r) {
    asm volatile("ldmatrix.sync.aligned.m8n8.x4.shared.b16 {%0,%1,%2,%3}, [%4];"
                 : "=r"(r[0]), "=r"(r[1]), "=r"(r[2]), "=r"(r[3]) : "r"(addr));
}
__device__ __forceinline__ void mma16816(float* d, const uint32_t* a, const uint32_t* b) {
    asm volatile("mma.sync.aligned.m16n8k16.row.col.f32.bf16.bf16.f32 "
                 "{%0,%1,%2,%3}, {%4,%5,%6,%7}, {%8,%9}, {%0,%1,%2,%3};"
                 : "+f"(d[0]), "+f"(d[1]), "+f"(d[2]), "+f"(d[3])
                 : "r"(a[0]), "r"(a[1]), "r"(a[2]), "r"(a[3]), "r"(b[0]), "r"(b[1]));
}
__device__ __forceinline__ void cp_async16(uint32_t dst, const void* src) {
    asm volatile("cp.async.cg.shared.global [%0], [%1], 16;" :: "r"(dst), "l"(src) : "memory");
}
__device__ __forceinline__ float fast_sigmoid(float x) {
    return __fdividef(1.f, 1.f + __expf(-x));
}
__device__ __forceinline__ float fast_tanh(float x) {
    return 1.f - __fdividef(2.f, __expf(2.f * x) + 1.f);
}

// ---------------- pack weights (gate-interleaved packed rows) ----------------
__global__ void pack_kernel(const float* __restrict__ Wf, const float* __restrict__ bf,
                            const float* __restrict__ Wi, const float* __restrict__ bi,
                            const float* __restrict__ Wg, const float* __restrict__ bg,
                            const float* __restrict__ Wo, const float* __restrict__ bo,
                            const float* __restrict__ Wr, const float* __restrict__ br) {
    int idx = blockIdx.x * blockDim.x + threadIdx.x;
    int stride = gridDim.x * blockDim.x;
    for (int i = idx; i < NPRE * DD; i += stride) {
        int n = i / DD, d = i - n * DD;
        float v;
        if (n < NG) {
            int hcol = n >> 2, gate = n & 3;
            const float* W = (gate == 0) ? Wf : (gate == 1) ? Wi : (gate == 2) ? Wg : Wo;
            v = W[hcol * DH + d];
        } else {
            v = Wr[(n - NG) * DD + d];
        }
        __nv_bfloat16 hi = __float2bfloat16_rn(v);
        g_Wxhi[i] = hi;
        g_Wxlo[i] = __float2bfloat16_rn(v - __bfloat162float(hi));
    }
    for (int i = idx; i < NG * HH; i += stride) {
        int n = i / HH, k = i - n * HH;
        int hcol = n >> 2, gate = n & 3;
        const float* W = (gate == 0) ? Wf : (gate == 1) ? Wi : (gate == 2) ? Wg : Wo;
        float v = W[hcol * DH + DD + k];
        __nv_bfloat16 hi = __float2bfloat16_rn(v);
        g_Whhi[i] = hi;
        g_Whlo[i] = __float2bfloat16_rn(v - __bfloat162float(hi));
    }
    for (int i = idx; i < NPRE; i += stride) {
        float v;
        if (i < NG) {
            int hcol = i >> 2, gate = i & 3;
            v = (gate == 0) ? bf[hcol] : (gate == 1) ? bi[hcol] : (gate == 2) ? bg[hcol] : bo[hcol];
        } else {
            v = br[i - NG];
        }
        g_bias[i] = v;
    }
}

// ---------------- x -> bf16 hi/lo ----------------
__global__ void xcvt_kernel(const float* __restrict__ x) {
    int idx = blockIdx.x * blockDim.x + threadIdx.x;
    int stride = gridDim.x * blockDim.x;
    for (size_t i = idx; i < (size_t)NTB * DD; i += stride) {
        float v = x[i];
        __nv_bfloat16 hi = __float2bfloat16_rn(v);
        g_xhi[i] = hi;
        g_xlo[i] = __float2bfloat16_rn(v - __bfloat162float(hi));
    }
}

// ---------------- pre-activation GEMM (HMMA, split bf16) ----------------
#define P_ROW 40                         // padded row (bf16 elems) -> 80B stride
#define P_HALF (128 * P_ROW * 2)         // 10240 B per operand-half per stage
#define P_STAGE (4 * P_HALF)             // 40960 B
#define P_SMEM (2 * P_STAGE)             // 81920 B
__global__ void __launch_bounds__(512) pre_gemm_mma() {
    extern __shared__ char sm[];
    const uint32_t smb = smem_u32(sm);
    const int tid = threadIdx.x;
    const int wid = tid >> 5, lane = tid & 31;
    const int mw = wid & 3, nw = wid >> 2;          // warp tile: m32 x n32
    const int mbase = blockIdx.x * 128;             // 20 m-tiles
    const int nbase = blockIdx.y * 128;             // 256 n-tiles

    const int o = tid >> 7, r = tid & 127;
    const __nv_bfloat16* gsrc =
        (o == 0) ? g_Wxhi + (size_t)(mbase + r) * DD :
        (o == 1) ? g_Wxlo + (size_t)(mbase + r) * DD :
        (o == 2) ? g_xhi + (size_t)(nbase + r) * DD :
                   g_xlo + (size_t)(nbase + r) * DD;
    const uint32_t sdst = smb + o * P_HALF + r * 80;

    const int aRow = mw * 32 + ((lane >> 3) & 1) * 8 + (lane & 7);
    const uint32_t aOff = (uint32_t)(aRow * 80 + ((lane >> 4) * 8) * 2);
    const int g8 = lane >> 3;
    uint32_t bOff[2];
#pragma unroll
    for (int pair = 0; pair < 2; pair++) {
        int nRow = nw * 32 + (pair * 2 + (g8 >> 1)) * 8 + (lane & 7);
        bOff[pair] = (uint32_t)(nRow * 80 + ((g8 & 1) * 8) * 2);
    }

    float acc[2][4][4];
#pragma unroll
    for (int i = 0; i < 2; i++)
#pragma unroll
        for (int j = 0; j < 4; j++)
#pragma unroll
            for (int q = 0; q < 4; q++) acc[i][j][q] = 0.f;

    uint4 pf[4];
    auto gload = [&](int chunk) {
        const __nv_bfloat16* p = gsrc + chunk * 32;
#pragma unroll
        for (int j = 0; j < 4; j++) pf[j] = *(const uint4*)(p + j * 8);
    };
    auto sstore = [&](int buf) {
        uint32_t d = sdst + buf * P_STAGE;
#pragma unroll
        for (int j = 0; j < 4; j++)
            *(uint4*)(sm + (d - smb) + j * 16) = pf[j];
    };
    auto do_mma = [&](int buf) {
        uint32_t base = smb + buf * P_STAGE;
#pragma unroll
        for (int kt = 0; kt < 2; kt++) {
            uint32_t ko = kt * 32;
            uint32_t aHi[2][4], aLo[2][4], bHi[4][2], bLo[4][2];
#pragma unroll
            for (int mt = 0; mt < 2; mt++) {
                ldsm4(base + 0 * P_HALF + aOff + mt * 16 * 80 + ko, aHi[mt]);
                ldsm4(base + 1 * P_HALF + aOff + mt * 16 * 80 + ko, aLo[mt]);
            }
#pragma unroll
            for (int pair = 0; pair < 2; pair++) {
                uint32_t t4[4];
                ldsm4(base + 2 * P_HALF + bOff[pair] + ko, t4);
                bHi[pair * 2][0] = t4[0]; bHi[pair * 2][1] = t4[1];
                bHi[pair * 2 + 1][0] = t4[2]; bHi[pair * 2 + 1][1] = t4[3];
                ldsm4(base + 3 * P_HALF + bOff[pair] + ko, t4);
                bLo[pair * 2][0] = t4[0]; bLo[pair * 2][1] = t4[1];
                bLo[pair * 2 + 1][0] = t4[2]; bLo[pair * 2 + 1][1] = t4[3];
            }
#pragma unroll
            for (int mt = 0; mt < 2; mt++)
#pragma unroll
                for (int nt = 0; nt < 4; nt++) {
                    mma16816(acc[mt][nt], aHi[mt], bHi[nt]);
                    mma16816(acc[mt][nt], aHi[mt], bLo[nt]);
                    mma16816(acc[mt][nt], aLo[mt], bHi[nt]);
                }
        }
    };

    gload(0); sstore(0);
    gload(1);
    __syncthreads();
    for (int c = 0; c < 16; c++) {
        if (c + 1 < 16) sstore((c + 1) & 1);
        if (c + 2 < 16) gload(c + 2);
        do_mma(c & 1);
        __syncthreads();
    }

    float* smf = (float*)sm;
#pragma unroll
    for (int mt = 0; mt < 2; mt++)
#pragma unroll
        for (int nt = 0; nt < 4; nt++) {
            int c0 = nw * 32 + nt * 8 + 2 * (lane & 3);
            int r0 = mw * 32 + mt * 16 + (lane >> 2);
            smf[c0 * 132 + r0] = acc[mt][nt][0];
            smf[(c0 + 1) * 132 + r0] = acc[mt][nt][1];
            smf[c0 * 132 + r0 + 8] = acc[mt][nt][2];
            smf[(c0 + 1) * 132 + r0 + 8] = acc[mt][nt][3];
        }
    __syncthreads();
#pragma unroll
    for (int j = 0; j < 8; j++) {
        int idx = j * 512 + tid;
        int c = idx >> 5, seg = idx & 31;
        float4 v = *(const float4*)(smf + c * 132 + seg * 4);
        float4 bv = *(const float4*)&g_bias[mbase + seg * 4];
        v.x += bv.x; v.y += bv.y; v.z += bv.z; v.w += bv.w;
        *(float4*)&g_pre[(size_t)(nbase + c) * NPRE + mbase + seg * 4] = v;
    }
}

// ---------------- acquire/release group barrier, all-thread polling ----------------
__device__ __forceinline__ unsigned bar_read_gen(int grp) {
    unsigned v;
    asm volatile("ld.relaxed.gpu.global.u32 %0, [%1];"
                 : "=r"(v) : "l"(&g_barg[grp * 32]));
    return v;
}
__device__ __forceinline__ void bar_arrive(int grp) {
    __syncthreads();                      // order all threads' h stores before release
    if (threadIdx.x == 0) {
        unsigned ticket;
        asm volatile("atom.acq_rel.gpu.global.add.u32 %0, [%1], 1;"
                     : "=r"(ticket) : "l"(&g_barc[grp * 32]) : "memory");
        if (ticket == 31) {
            asm volatile("st.relaxed.gpu.global.u32 [%0], %1;"
                         :: "l"(&g_barc[grp * 32]), "r"(0u) : "memory");
            asm volatile("red.release.gpu.global.add.u32 [%0], 1;"
                         :: "l"(&g_barg[grp * 32]) : "memory");
        }
    }
}
__device__ __forceinline__ void bar_wait_all(int grp, unsigned old) {
    unsigned v;
    do {
        asm volatile("ld.relaxed.gpu.global.u32 %0, [%1];"
                     : "=r"(v) : "l"(&g_barg[grp * 32]) : "memory");
    } while (v == old);
    asm volatile("ld.acquire.gpu.global.u32 %0, [%1];"
                 : "=r"(v) : "l"(&g_barg[grp * 32]) : "memory");
}

// ---------------- persistent LSTM recurrence (HMMA, W resident in smem) ----------------
#define R_WROW 520                       // padded k (bf16) -> 1040B stride
#define R_OWHI 0
#define R_OWLO (64 * R_WROW * 2)         // 66560
#define R_OBHI (2 * 64 * R_WROW * 2)     // 133120
#define R_OBLO (R_OBHI + 16 * R_WROW * 2)
#define R_OACC (R_OBHI + 2 * 16 * R_WROW * 2)
#define R_SMEM (R_OACC + 64 * 17 * 4)    // sAcc[64 rows][16 b] pitch 17
__global__ void __launch_bounds__(256) lstm_persistent(float* __restrict__ out) {
    extern __shared__ char sm[];
    const uint32_t smb = smem_u32(sm);
    const int tid = threadIdx.x;
    const int wid = tid >> 5, lane = tid & 31;
    const int cta = blockIdx.x;
    const int rb = cta & 31;             // 16 hcols: rb*16..
    const int bblk = cta >> 5;           // group: 16 b = bblk*16..
    const int mw = wid & 3;              // m16 tile within 64 rows
    const int nw = wid >> 2;             // b8 tile within 16 b

    // ---- load resident W slice (packed rows rb*64..+63), full k ----
    for (int i = tid; i < 64 * 64 * 2; i += 256) {
        int hf = i >> 12;
        int rem = i & 4095;
        int r = rem >> 6, s = rem & 63;
        const __nv_bfloat16* src = (hf ? g_Whlo : g_Whhi) + (size_t)(rb * 64 + r) * HH + s * 8;
        *(uint4*)(sm + (hf ? R_OWLO : R_OWHI) + r * (R_WROW * 2) + s * 16) = *(const uint4*)src;
    }

    // ldmatrix lane offsets
    const int aRow = mw * 16 + ((lane >> 3) & 1) * 8 + (lane & 7);
    const uint32_t aOff = (uint32_t)(aRow * (R_WROW * 2) + ((lane >> 4) * 8) * 2);
    const int bRow = nw * 8 + (lane & 7);            // ldsm4 over k32
    const uint32_t bOff = (uint32_t)(bRow * (R_WROW * 2) + ((lane >> 3) * 8) * 2);

    // cell-update lane mapping: hcol contiguous within warp (coalesced I/O)
    const int hc_l = lane & 15;                      // 0..15
    const int bsel = wid * 2 + (lane >> 4);          // 0..15
    const int hcol = rb * 16 + hc_l;
    const int b = bblk * 16 + bsel;
    float* sAcc = (float*)(sm + R_OACC);             // [r 0..63][b 0..15], pitch 17

    float cst = 0.f;
    float hlast = 0.f;
    unsigned bold = 0;

    float4 pg;
    float rv;
    {
        const size_t cb = (size_t)(0 * BB + b) * NPRE;
        pg = __ldcs((const float4*)&g_pre[cb + hcol * 4]);
        rv = __ldcs(&g_pre[cb + NG + hcol]);
    }

    __syncthreads();

    for (int t = 0; t < TT; t++) {
        float gv0 = 0.f, gv1 = 0.f, gv2 = 0.f, gv3 = 0.f;
        if (t > 0) {
            bar_wait_all(bblk, bold);
            const int rbuf = (t - 1) & 1;
            // stage h slice in 2 k-chunks of 256, progressive wait
#pragma unroll
            for (int c = 0; c < 2; c++) {
#pragma unroll
                for (int j = 0; j < 4; j++) {
                    int i = tid + j * 256;           // 0..1023
                    int hf = i >> 9;
                    int rem = i & 511;
                    int r = rem >> 5, s = (rem & 31) + c * 32;
                    const void* src = (const void*)((hf ? g_hlo : g_hhi) + rbuf * BB * HH +
                                                    (size_t)(bblk * 16 + r) * HH + s * 8);
                    cp_async16(smb + (hf ? R_OBLO : R_OBHI) + r * (R_WROW * 2) + s * 16, src);
                }
                asm volatile("cp.async.commit_group;" ::: "memory");
            }

            float aA0[4] = {}, aB0[4] = {}, aC0[4] = {};
            float aA1[4] = {}, aB1[4] = {}, aC1[4] = {};

            asm volatile("cp.async.wait_group 1;" ::: "memory");
            __syncthreads();
#pragma unroll 4
            for (int kt2 = 0; kt2 < 8; kt2++) {
                uint32_t ko = kt2 * 64;
                uint32_t aHi0[4], aHi1[4], aLo0[4], aLo1[4], bH[4], bL[4];
                ldsm4(smb + R_OWHI + aOff + ko, aHi0);
                ldsm4(smb + R_OWHI + aOff + ko + 32, aHi1);
                ldsm4(smb + R_OWLO + aOff + ko, aLo0);
                ldsm4(smb + R_OWLO + aOff + ko + 32, aLo1);
                ldsm4(smb + R_OBHI + bOff + ko, bH);
                ldsm4(smb + R_OBLO + bOff + ko, bL);
                mma16816(aA0, aHi0, bH);
                mma16816(aB0, aHi0, bL);
                mma16816(aC0, aLo0, bH);
                mma16816(aA1, aHi1, bH + 2);
                mma16816(aB1, aHi1, bL + 2);
                mma16816(aC1, aLo1, bH + 2);
            }
            asm volatile("cp.async.wait_group 0;" ::: "memory");
            __syncthreads();
#pragma unroll 4
            for (int kt2 = 8; kt2 < 16; kt2++) {
                uint32_t ko = kt2 * 64;
                uint32_t aHi0[4], aHi1[4], aLo0[4], aLo1[4], bH[4], bL[4];
                ldsm4(smb + R_OWHI + aOff + ko, aHi0);
                ldsm4(smb + R_OWHI + aOff + ko + 32, aHi1);
                ldsm4(smb + R_OWLO + aOff + ko, aLo0);
                ldsm4(smb + R_OWLO + aOff + ko + 32, aLo1);
                ldsm4(smb + R_OBHI + bOff + ko, bH);
                ldsm4(smb + R_OBLO + bOff + ko, bL);
                mma16816(aA0, aHi0, bH);
                mma16816(aB0, aHi0, bL);
                mma16816(aC0, aLo0, bH);
                mma16816(aA1, aHi1, bH + 2);
                mma16816(aB1, aHi1, bL + 2);
                mma16816(aC1, aLo1, bH + 2);
            }
            {
                int r0 = mw * 16 + (lane >> 2);
                int c0 = nw * 8 + 2 * (lane & 3);
                sAcc[r0 * 17 + c0]           = aA0[0] + aB0[0] + aC0[0] + aA1[0] + aB1[0] + aC1[0];
                sAcc[r0 * 17 + c0 + 1]       = aA0[1] + aB0[1] + aC0[1] + aA1[1] + aB1[1] + aC1[1];
                sAcc[(r0 + 8) * 17 + c0]     = aA0[2] + aB0[2] + aC0[2] + aA1[2] + aB1[2] + aC1[2];
                sAcc[(r0 + 8) * 17 + c0 + 1] = aA0[3] + aB0[3] + aC0[3] + aA1[3] + aB1[3] + aC1[3];
            }
            __syncthreads();
            gv0 = sAcc[(hc_l * 4 + 0) * 17 + bsel];
            gv1 = sAcc[(hc_l * 4 + 1) * 17 + bsel];
            gv2 = sAcc[(hc_l * 4 + 2) * 17 + bsel];
            gv3 = sAcc[(hc_l * 4 + 3) * 17 + bsel];
        }

        float fp = pg.x + gv0, ip = pg.y + gv1, gp = pg.z + gv2, op = pg.w + gv3;
        float f = fast_sigmoid(fp);
        float ii = fast_sigmoid(ip);
        float gg = fast_tanh(gp);
        float oo = fast_sigmoid(op);
        cst = f * cst + ii * gg;
        float h = oo * fast_tanh(cst) + rv;
        hlast = h;

        const int wbuf = t & 1;
        __nv_bfloat16 hhi = __float2bfloat16_rn(h);
        __nv_bfloat16 hlo = __float2bfloat16_rn(h - __bfloat162float(hhi));
        {
            unsigned short uhi = *(unsigned short*)&hhi;
            unsigned short ulo = *(unsigned short*)&hlo;
            asm volatile("st.global.cg.u16 [%0], %1;"
                         :: "l"(&g_hhi[wbuf * BB * HH + b * HH + hcol]), "h"(uhi) : "memory");
            asm volatile("st.global.cg.u16 [%0], %1;"
                         :: "l"(&g_hlo[wbuf * BB * HH + b * HH + hcol]), "h"(ulo) : "memory");
        }

        if (t + 1 < TT) {
            bold = bar_read_gen(bblk);
            bar_arrive(bblk);
            out[(size_t)t * BB * HH + (size_t)b * HH + hcol] = h;
            const size_t cb = (size_t)((t + 1) * BB + b) * NPRE;
            pg = __ldcs((const float4*)&g_pre[cb + hcol * 4]);
            rv = __ldcs(&g_pre[cb + NG + hcol]);
        } else {
            out[(size_t)t * BB * HH + (size_t)b * HH + hcol] = h;
        }
    }

    out[(size_t)TT * BB * HH + (size_t)b * HH + hcol] = hlast;
    out[(size_t)TT * BB * HH + BB * HH + (size_t)b * HH + hcol] = cst;
}

extern "C" void kernel_launch(void* const* d_in, const int* in_sizes, int n_in,
                              void* d_out, int out_size) {
    const float* x  = (const float*)d_in[0];
    const float* Wf = (const float*)d_in[1];
    const float* bf = (const float*)d_in[2];
    const float* Wi = (const float*)d_in[3];
    const float* bi = (const float*)d_in[4];
    const float* Wg = (const float*)d_in[5];
    const float* bg = (const float*)d_in[6];
    const float* Wo = (const float*)d_in[7];
    const float* bo = (const float*)d_in[8];
    const float* Wr = (const float*)d_in[9];
    const float* br = (const float*)d_in[10];
    float* out = (float*)d_out;

    static int inited = 0;
    if (!inited) {
        cudaFuncSetAttribute(pre_gemm_mma, cudaFuncAttributeMaxDynamicSharedMemorySize, P_SMEM);
        cudaFuncSetAttribute(lstm_persistent, cudaFuncAttributeMaxDynamicSharedMemorySize, R_SMEM);
        inited = 1;
    }

    pack_kernel<<<256, 256>>>(Wf, bf, Wi, bi, Wg, bg, Wo, bo, Wr, br);
    xcvt_kernel<<<512, 256>>>(x);
    pre_gemm_mma<<<dim3(NPRE / 128, NTB / 128), 512, P_SMEM>>>();
    lstm_persistent<<<NCTA, 256, R_SMEM>>>(out);
}